// round 1
// baseline (speedup 1.0000x reference)
#include <cuda_runtime.h>
#include <cstdint>

#define NN 100000
#define EE 200000
#define BBATCH 2048
#define HH 256
#define HB2 512
#define LLAYERS 4

// ------------------------- scratch (device globals; no allocs) ---------------
__device__ float g_h[(size_t)NN * HH];     // node state
__device__ float g_hn[(size_t)NN * HH];    // relu(LN(h))
__device__ float g_tmp[(size_t)NN * HH];   // genconv aggregation output (+residual)
__device__ float g_mid[(size_t)NN * HB2];  // MLP hidden
__device__ float g_vn[BBATCH * HH];
__device__ float g_vnsum[BBATCH * HH];
__device__ float g_inv[BBATCH];
__device__ int g_deg[NN];
__device__ int g_indptr[NN + 1];
__device__ int g_cursor[NN];
__device__ int g_csr[EE];
__device__ int g_cnt[BBATCH];
__device__ int g_bsums[128];
__device__ int g_boffs[128];

// ------------------------- small helpers -------------------------------------
__device__ __forceinline__ uint32_t f2tf(float f) {
    uint32_t r;
    asm("cvt.rna.tf32.f32 %0, %1;" : "=r"(r) : "f"(f));
    return r;
}

__device__ __forceinline__ void mma_tf32(float* c, const uint32_t* a, const uint32_t* b) {
    asm volatile(
        "mma.sync.aligned.m16n8k8.row.col.f32.tf32.tf32.f32 "
        "{%0,%1,%2,%3},{%4,%5,%6,%7},{%8,%9},{%0,%1,%2,%3};"
        : "+f"(c[0]), "+f"(c[1]), "+f"(c[2]), "+f"(c[3])
        : "r"(a[0]), "r"(a[1]), "r"(a[2]), "r"(a[3]), "r"(b[0]), "r"(b[1]));
}

// ------------------------- setup kernels -------------------------------------
__global__ void zero_setup() {
    int i = blockIdx.x * blockDim.x + threadIdx.x;
    if (i < NN) { g_deg[i] = 0; g_cursor[i] = 0; }
    if (i < BBATCH) g_cnt[i] = 0;
}

__global__ void zero_f(float* p, int n) {
    int i = blockIdx.x * blockDim.x + threadIdx.x;
    if (i < n) p[i] = 0.0f;
}

__global__ void count_deg(const int* __restrict__ dst) {
    int e = blockIdx.x * blockDim.x + threadIdx.x;
    if (e < EE) atomicAdd(&g_deg[dst[e]], 1);
}

__global__ void count_batch(const int* __restrict__ batch) {
    int n = blockIdx.x * blockDim.x + threadIdx.x;
    if (n < NN) atomicAdd(&g_cnt[batch[n]], 1);
}

__global__ void scan_block() {  // 98 blocks x 1024
    __shared__ int s[1024];
    int i = blockIdx.x * 1024 + threadIdx.x;
    int v = (i < NN) ? g_deg[i] : 0;
    s[threadIdx.x] = v;
    __syncthreads();
#pragma unroll
    for (int off = 1; off < 1024; off <<= 1) {
        int t = (threadIdx.x >= off) ? s[threadIdx.x - off] : 0;
        __syncthreads();
        s[threadIdx.x] += t;
        __syncthreads();
    }
    if (i < NN) g_indptr[i + 1] = s[threadIdx.x];
    if (threadIdx.x == 1023) g_bsums[blockIdx.x] = s[1023];
    if (i == 0) g_indptr[0] = 0;
}

__global__ void scan_sums(int nb) {  // 1 block x 128
    __shared__ int s[128];
    int t = threadIdx.x;
    int v = (t < nb) ? g_bsums[t] : 0;
    s[t] = v;
    __syncthreads();
#pragma unroll
    for (int off = 1; off < 128; off <<= 1) {
        int u = (t >= off) ? s[t - off] : 0;
        __syncthreads();
        s[t] += u;
        __syncthreads();
    }
    if (t < nb) g_boffs[t] = s[t] - v;  // exclusive offset for block t
}

__global__ void add_offs() {
    int i = blockIdx.x * blockDim.x + threadIdx.x;
    if (i < NN) g_indptr[i + 1] += g_boffs[i >> 10];
}

__global__ void csr_fill(const int* __restrict__ dst) {
    int e = blockIdx.x * blockDim.x + threadIdx.x;
    if (e < EE) {
        int d = dst[e];
        int p = atomicAdd(&g_cursor[d], 1);
        g_csr[g_indptr[d] + p] = e;
    }
}

__global__ void calc_inv() {
    int b = blockIdx.x * blockDim.x + threadIdx.x;
    if (b < BBATCH) g_inv[b] = 1.0f / fmaxf((float)g_cnt[b], 1.0f);
}

__global__ void vn_init(float* __restrict__ vn, const float* __restrict__ emb) {
    int i = blockIdx.x * blockDim.x + threadIdx.x;
    if (i < BBATCH * HH) vn[i] = emb[i & (HH - 1)];
}

// ------------------------- node encoder: h = x @ node_W + node_b -------------
__global__ void node_enc(const float* __restrict__ x, const float* __restrict__ W,
                         const float* __restrict__ b, float* __restrict__ h) {
    __shared__ float xs[9];
    int n = blockIdx.x;
    if (threadIdx.x < 9) xs[threadIdx.x] = x[n * 9 + threadIdx.x];
    __syncthreads();
    int c = threadIdx.x;
    float acc = b[c];
#pragma unroll
    for (int k = 0; k < 9; k++) acc += xs[k] * W[k * HH + c];
    h[(size_t)n * HH + c] = acc;
}

// ------------------------- LayerNorm + ReLU (warp per row) -------------------
template <int HD>
__global__ void ln_relu(const float* __restrict__ src, float* __restrict__ dst,
                        const float* __restrict__ g, const float* __restrict__ b) {
    constexpr int PER = HD / 32;
    int warp = (blockIdx.x * blockDim.x + threadIdx.x) >> 5;
    int lane = threadIdx.x & 31;
    if (warp >= NN) return;
    const float* row = src + (size_t)warp * HD;
    float v[PER];
    float s = 0.f, s2 = 0.f;
#pragma unroll
    for (int j = 0; j < PER / 4; j++) {
        float4 t = *(const float4*)(row + j * 128 + lane * 4);
        v[j * 4 + 0] = t.x; v[j * 4 + 1] = t.y; v[j * 4 + 2] = t.z; v[j * 4 + 3] = t.w;
    }
#pragma unroll
    for (int j = 0; j < PER; j++) { s += v[j]; s2 += v[j] * v[j]; }
#pragma unroll
    for (int o = 16; o > 0; o >>= 1) {
        s += __shfl_xor_sync(0xffffffffu, s, o);
        s2 += __shfl_xor_sync(0xffffffffu, s2, o);
    }
    float mu = s / HD;
    float var = s2 / HD - mu * mu;
    float r = rsqrtf(var + 1e-5f);
    float* orow = dst + (size_t)warp * HD;
#pragma unroll
    for (int j = 0; j < PER / 4; j++) {
        float4 o;
        int c = j * 128 + lane * 4;
        o.x = fmaxf((v[j * 4 + 0] - mu) * r * g[c + 0] + b[c + 0], 0.f);
        o.y = fmaxf((v[j * 4 + 1] - mu) * r * g[c + 1] + b[c + 1], 0.f);
        o.z = fmaxf((v[j * 4 + 2] - mu) * r * g[c + 2] + b[c + 2], 0.f);
        o.w = fmaxf((v[j * 4 + 3] - mu) * r * g[c + 3] + b[c + 3], 0.f);
        *(float4*)(orow + c) = o;
    }
}

// ------------- GENConv aggregation: CSR + online softmax, warp per node ------
// Fuses the edge encoder: ea = edge_attr @ edge_W + edge_b (K=3) on the fly.
__global__ void aggregate(const float* __restrict__ hn, const int* __restrict__ src,
                          const float* __restrict__ eattr, const float* __restrict__ eW,
                          const float* __restrict__ eb, const float* __restrict__ tptr,
                          float* __restrict__ outp) {
    __shared__ float sW[3 * HH];
    __shared__ float sb[HH];
    for (int i = threadIdx.x; i < 3 * HH; i += blockDim.x) sW[i] = eW[i];
    for (int i = threadIdx.x; i < HH; i += blockDim.x) sb[i] = eb[i];
    __syncthreads();
    int warp = blockIdx.x * (blockDim.x >> 5) + (threadIdx.x >> 5);
    int lane = threadIdx.x & 31;
    if (warp >= NN) return;
    float tval = *tptr;
    int e0 = g_indptr[warp], e1 = g_indptr[warp + 1];
    float m[8], d[8], a[8];
#pragma unroll
    for (int j = 0; j < 8; j++) { m[j] = -1e30f; d[j] = 0.f; a[j] = 0.f; }

    for (int e = e0; e < e1; e++) {
        int eid = g_csr[e];
        int u = src[eid];
        float e0a = eattr[eid * 3 + 0];
        float e1a = eattr[eid * 3 + 1];
        float e2a = eattr[eid * 3 + 2];
        const float* hrow = hn + (size_t)u * HH;
#pragma unroll
        for (int gI = 0; gI < 2; gI++) {
            float4 hv = *(const float4*)(hrow + gI * 128 + lane * 4);
            float hvv[4] = {hv.x, hv.y, hv.z, hv.w};
#pragma unroll
            for (int q = 0; q < 4; q++) {
                int c = gI * 128 + lane * 4 + q;
                float ea = sb[c] + e0a * sW[c] + e1a * sW[HH + c] + e2a * sW[2 * HH + c];
                float msg = fmaxf(hvv[q] + ea, 0.f) + 1e-7f;
                float sc = msg * tval;
                int j = gI * 4 + q;
                float mn = fmaxf(m[j], sc);
                float em = __expf(m[j] - mn);
                float es = __expf(sc - mn);
                d[j] = d[j] * em + es;
                a[j] = a[j] * em + msg * es;
                m[j] = mn;
            }
        }
    }
    float* orow = outp + (size_t)warp * HH;
    const float* hnrow = hn + (size_t)warp * HH;
#pragma unroll
    for (int gI = 0; gI < 2; gI++) {
        float4 hv = *(const float4*)(hnrow + gI * 128 + lane * 4);
        float4 o;
        o.x = a[gI * 4 + 0] / (d[gI * 4 + 0] + 1e-16f) + hv.x;
        o.y = a[gI * 4 + 1] / (d[gI * 4 + 1] + 1e-16f) + hv.y;
        o.z = a[gI * 4 + 2] / (d[gI * 4 + 2] + 1e-16f) + hv.z;
        o.w = a[gI * 4 + 3] / (d[gI * 4 + 3] + 1e-16f) + hv.w;
        *(float4*)(orow + gI * 128 + lane * 4) = o;
    }
}

// ---------------- tf32 mma.sync GEMM: C = A[M,K] @ W[K,Nc] + bias ------------
// BM=BN=128, BK=16, 8 warps, warp tile 32x64 (2x8 m16n8k8 per k-step).
__global__ __launch_bounds__(256) void gemm_tf32_k(
    const float* __restrict__ A, const float* __restrict__ W,
    const float* __restrict__ bias, float* __restrict__ C,
    int M, int K, int Nc, int accum) {
    __shared__ __align__(16) uint32_t As[16][136];  // [k][m], stride 136 -> conflict-free frag loads
    __shared__ __align__(16) uint32_t Bs[16][136];  // [k][n]
    int tid = threadIdx.x;
    int lane = tid & 31, warp = tid >> 5;
    int wm = warp >> 1, wn = warp & 1;
    int bm = blockIdx.y * 128, bn = blockIdx.x * 128;
    float acc[2][8][4];
#pragma unroll
    for (int mi = 0; mi < 2; mi++)
#pragma unroll
        for (int ni = 0; ni < 8; ni++)
#pragma unroll
            for (int q = 0; q < 4; q++) acc[mi][ni][q] = 0.f;

    for (int k0 = 0; k0 < K; k0 += 16) {
        __syncthreads();
        // A tile 128x16 -> As[k][m]
#pragma unroll
        for (int p = 0; p < 2; p++) {
            int lin = p * 256 + tid;
            int row = lin >> 2, c4 = lin & 3;
            float4 v = make_float4(0.f, 0.f, 0.f, 0.f);
            int gr = bm + row;
            if (gr < M) v = *(const float4*)(A + (size_t)gr * K + k0 + c4 * 4);
            As[c4 * 4 + 0][row] = f2tf(v.x);
            As[c4 * 4 + 1][row] = f2tf(v.y);
            As[c4 * 4 + 2][row] = f2tf(v.z);
            As[c4 * 4 + 3][row] = f2tf(v.w);
        }
        // B tile 16x128 -> Bs[k][n]
#pragma unroll
        for (int p = 0; p < 2; p++) {
            int lin = p * 256 + tid;
            int kr = lin >> 5, n4 = lin & 31;
            float4 v = *(const float4*)(W + (size_t)(k0 + kr) * Nc + bn + n4 * 4);
            uint4 u;
            u.x = f2tf(v.x); u.y = f2tf(v.y); u.z = f2tf(v.z); u.w = f2tf(v.w);
            *reinterpret_cast<uint4*>(&Bs[kr][n4 * 4]) = u;
        }
        __syncthreads();
#pragma unroll
        for (int k8 = 0; k8 < 16; k8 += 8) {
            uint32_t af[2][4];
            int kk = k8 + (lane & 3);
#pragma unroll
            for (int mi = 0; mi < 2; mi++) {
                int mr = wm * 32 + mi * 16 + (lane >> 2);
                af[mi][0] = As[kk][mr];
                af[mi][1] = As[kk][mr + 8];
                af[mi][2] = As[kk + 4][mr];
                af[mi][3] = As[kk + 4][mr + 8];
            }
            uint32_t bf[8][2];
#pragma unroll
            for (int ni = 0; ni < 8; ni++) {
                int nc = wn * 64 + ni * 8 + (lane >> 2);
                bf[ni][0] = Bs[kk][nc];
                bf[ni][1] = Bs[kk + 4][nc];
            }
#pragma unroll
            for (int mi = 0; mi < 2; mi++)
#pragma unroll
                for (int ni = 0; ni < 8; ni++) mma_tf32(acc[mi][ni], af[mi], bf[ni]);
        }
    }
    // epilogue
#pragma unroll
    for (int mi = 0; mi < 2; mi++) {
#pragma unroll
        for (int rr = 0; rr < 2; rr++) {
            int row = bm + wm * 32 + mi * 16 + (lane >> 2) + rr * 8;
            if (row >= M) continue;
#pragma unroll
            for (int ni = 0; ni < 8; ni++) {
                int col = bn + wn * 64 + ni * 8 + (lane & 3) * 2;
                float2 v;
                v.x = acc[mi][ni][rr * 2 + 0] + bias[col];
                v.y = acc[mi][ni][rr * 2 + 1] + bias[col + 1];
                float* p = C + (size_t)row * Nc + col;
                if (accum) { v.x += p[0]; v.y += p[1]; }
                *(float2*)p = v;
            }
        }
    }
}

// ------------- pooling over sorted batch (run-length + few atomics) ----------
__global__ void pool_sum(const float* __restrict__ src, const int* __restrict__ batch,
                         float* __restrict__ out) {
    __shared__ int sb[512];
    int n0 = blockIdx.x * 512;
    int nend = min(n0 + 512, NN);
    for (int i = threadIdx.x; i < nend - n0; i += 256) sb[i] = batch[n0 + i];
    __syncthreads();
    int c = threadIdx.x;
    float acc = 0.f;
    int cur = sb[0];
    for (int n = n0; n < nend; n++) {
        int b = sb[n - n0];
        if (b != cur) {
            atomicAdd(&out[(size_t)cur * HH + c], acc);
            acc = 0.f;
            cur = b;
        }
        acc += src[(size_t)n * HH + c];
    }
    atomicAdd(&out[(size_t)cur * HH + c], acc);
}

__global__ void vn_update(float* __restrict__ vn, const float* __restrict__ vnsum,
                          const float* __restrict__ inv) {
    int i = blockIdx.x * blockDim.x + threadIdx.x;
    if (i < BBATCH * HH) vn[i] += vnsum[i] * inv[i >> 8];
}

__global__ void add_vn(float* __restrict__ h, const int* __restrict__ batch,
                       const float* __restrict__ vn) {
    int i = blockIdx.x * blockDim.x + threadIdx.x;
    if (i < NN * HH) {
        int n = i >> 8, c = i & 255;
        h[i] += vn[((size_t)batch[n] << 8) + c];
    }
}

__global__ void scale_out(float* __restrict__ out, const float* __restrict__ inv) {
    int i = blockIdx.x * blockDim.x + threadIdx.x;
    if (i < BBATCH * HH) out[i] *= inv[i >> 8];
}

// ------------------------------ host orchestration ---------------------------
extern "C" void kernel_launch(void* const* d_in, const int* in_sizes, int n_in,
                              void* d_out, int out_size) {
    const float* x = (const float*)d_in[0];
    const int* eidx = (const int*)d_in[1];
    const float* eattr = (const float*)d_in[2];
    const int* batch = (const int*)d_in[3];
    const float* node_W = (const float*)d_in[4];
    const float* node_b = (const float*)d_in[5];
    const float* edge_W = (const float*)d_in[6];
    const float* edge_b = (const float*)d_in[7];
    const float* vn_emb = (const float*)d_in[8];
    const float* ln_g = (const float*)d_in[9];
    const float* ln_b = (const float*)d_in[10];
    const float* tt = (const float*)d_in[11];
    const float* W1 = (const float*)d_in[12];
    const float* b1 = (const float*)d_in[13];
    const float* mg = (const float*)d_in[14];
    const float* mb = (const float*)d_in[15];
    const float* W2 = (const float*)d_in[16];
    const float* b2 = (const float*)d_in[17];
    float* out = (float*)d_out;
    const int* srcp = eidx;
    const int* dstp = eidx + EE;

    float *h_, *hn_, *tmp_, *mid_, *vn_, *vnsum_, *inv_;
    cudaGetSymbolAddress((void**)&h_, g_h);
    cudaGetSymbolAddress((void**)&hn_, g_hn);
    cudaGetSymbolAddress((void**)&tmp_, g_tmp);
    cudaGetSymbolAddress((void**)&mid_, g_mid);
    cudaGetSymbolAddress((void**)&vn_, g_vn);
    cudaGetSymbolAddress((void**)&vnsum_, g_vnsum);
    cudaGetSymbolAddress((void**)&inv_, g_inv);

    const int NB_SCAN = (NN + 1023) / 1024;  // 98

    // ---- setup: counts, CSR, inv, vn, encoder ----
    zero_setup<<<(NN + 255) / 256, 256>>>();
    count_deg<<<(EE + 255) / 256, 256>>>(dstp);
    count_batch<<<(NN + 255) / 256, 256>>>(batch);
    scan_block<<<NB_SCAN, 1024>>>();
    scan_sums<<<1, 128>>>(NB_SCAN);
    add_offs<<<(NN + 255) / 256, 256>>>();
    csr_fill<<<(EE + 255) / 256, 256>>>(dstp);
    calc_inv<<<(BBATCH + 255) / 256, 256>>>();
    vn_init<<<(BBATCH * HH + 255) / 256, 256>>>(vn_, vn_emb);
    node_enc<<<NN, 256>>>(x, node_W, node_b, h_);

    // ---- layers 1..3 ----
    for (int l = 1; l < LLAYERS; l++) {
        ln_relu<HH><<<NN / 8, 256>>>(h_, hn_, ln_g + l * HH, ln_b + l * HH);
        aggregate<<<NN / 8, 256>>>(hn_, srcp, eattr, edge_W, edge_b, tt + (l - 1), tmp_);
        dim3 g1(HB2 / 128, (NN + 127) / 128);
        gemm_tf32_k<<<g1, 256>>>(tmp_, W1 + (size_t)(l - 1) * HH * HB2,
                                 b1 + (l - 1) * HB2, mid_, NN, HH, HB2, 0);
        ln_relu<HB2><<<NN / 8, 256>>>(mid_, mid_, mg + (l - 1) * HB2, mb + (l - 1) * HB2);
        dim3 g2(HH / 128, (NN + 127) / 128);
        gemm_tf32_k<<<g2, 256>>>(mid_, W2 + (size_t)(l - 1) * HB2 * HH,
                                 b2 + (l - 1) * HH, h_, NN, HB2, HH, 1);  // h += MLP out
        zero_f<<<(BBATCH * HH + 255) / 256, 256>>>(vnsum_, BBATCH * HH);
        pool_sum<<<(NN + 511) / 512, 256>>>(h_, batch, vnsum_);
        vn_update<<<(BBATCH * HH + 255) / 256, 256>>>(vn_, vnsum_, inv_);
        add_vn<<<(NN * HH + 255) / 256, 256>>>(h_, batch, vn_);
    }

    // ---- final norm + mean pool ----
    ln_relu<HH><<<NN / 8, 256>>>(h_, hn_, ln_g, ln_b);
    zero_f<<<(BBATCH * HH + 255) / 256, 256>>>(out, BBATCH * HH);
    pool_sum<<<(NN + 511) / 512, 256>>>(hn_, batch, out);
    scale_out<<<(BBATCH * HH + 255) / 256, 256>>>(out, inv_);
}

// round 2
// speedup vs baseline: 1.3761x; 1.3761x over previous
#include <cuda_runtime.h>
#include <cstdint>

#define NN 100000
#define EE 200000
#define BBATCH 2048
#define HH 256
#define HB2 512
#define LLAYERS 4

// ------------------------- scratch (device globals; no allocs) ---------------
__device__ float g_h[(size_t)NN * HH];     // node state
__device__ float g_hn[(size_t)NN * HH];    // relu(LN(h))
__device__ float g_tmp[(size_t)NN * HH];   // genconv aggregation output (+residual)
__device__ float g_mid[(size_t)NN * HB2];  // MLP hidden
__device__ float g_vn[BBATCH * HH];
__device__ float g_vnsum[BBATCH * HH];
__device__ float g_inv[BBATCH];
__device__ float g_w1c[3 * HH * HB2];      // tf32-rounded W1
__device__ float g_w2c[3 * HB2 * HH];      // tf32-rounded W2
__device__ int g_deg[NN];
__device__ int g_indptr[NN + 1];
__device__ int g_cursor[NN];
__device__ int g_csr[EE];
__device__ int g_cnt[BBATCH];
__device__ int g_bsums[128];
__device__ int g_boffs[128];

// ------------------------- small helpers -------------------------------------
__device__ __forceinline__ uint32_t f2tf(float f) {
    uint32_t r;
    asm("cvt.rna.tf32.f32 %0, %1;" : "=r"(r) : "f"(f));
    return r;
}

__device__ __forceinline__ void mma_tf32(float* c, const uint32_t* a, const uint32_t* b) {
    asm volatile(
        "mma.sync.aligned.m16n8k8.row.col.f32.tf32.tf32.f32 "
        "{%0,%1,%2,%3},{%4,%5,%6,%7},{%8,%9},{%0,%1,%2,%3};"
        : "+f"(c[0]), "+f"(c[1]), "+f"(c[2]), "+f"(c[3])
        : "r"(a[0]), "r"(a[1]), "r"(a[2]), "r"(a[3]), "r"(b[0]), "r"(b[1]));
}

__device__ __forceinline__ void cp16(uint32_t dst, const void* src, int bytes) {
    asm volatile("cp.async.cg.shared.global [%0], [%1], 16, %2;\n" ::"r"(dst), "l"(src),
                 "r"(bytes));
}
__device__ __forceinline__ void cp_commit() { asm volatile("cp.async.commit_group;\n"); }
template <int W>
__device__ __forceinline__ void cp_wait() {
    asm volatile("cp.async.wait_group %0;\n" ::"n"(W));
}

// ------------------------- setup kernels -------------------------------------
__global__ void zero_setup() {
    int i = blockIdx.x * blockDim.x + threadIdx.x;
    if (i < NN) { g_deg[i] = 0; g_cursor[i] = 0; }
    if (i < BBATCH) g_cnt[i] = 0;
}

__global__ void zero_f(float* p, int n) {
    int i = blockIdx.x * blockDim.x + threadIdx.x;
    if (i < n) p[i] = 0.0f;
}

__global__ void count_deg(const int* __restrict__ dst) {
    int e = blockIdx.x * blockDim.x + threadIdx.x;
    if (e < EE) atomicAdd(&g_deg[dst[e]], 1);
}

__global__ void count_batch(const int* __restrict__ batch) {
    int n = blockIdx.x * blockDim.x + threadIdx.x;
    if (n < NN) atomicAdd(&g_cnt[batch[n]], 1);
}

__global__ void scan_block() {  // 98 blocks x 1024
    __shared__ int s[1024];
    int i = blockIdx.x * 1024 + threadIdx.x;
    int v = (i < NN) ? g_deg[i] : 0;
    s[threadIdx.x] = v;
    __syncthreads();
#pragma unroll
    for (int off = 1; off < 1024; off <<= 1) {
        int t = (threadIdx.x >= off) ? s[threadIdx.x - off] : 0;
        __syncthreads();
        s[threadIdx.x] += t;
        __syncthreads();
    }
    if (i < NN) g_indptr[i + 1] = s[threadIdx.x];
    if (threadIdx.x == 1023) g_bsums[blockIdx.x] = s[1023];
    if (i == 0) g_indptr[0] = 0;
}

__global__ void scan_sums(int nb) {  // 1 block x 128
    __shared__ int s[128];
    int t = threadIdx.x;
    int v = (t < nb) ? g_bsums[t] : 0;
    s[t] = v;
    __syncthreads();
#pragma unroll
    for (int off = 1; off < 128; off <<= 1) {
        int u = (t >= off) ? s[t - off] : 0;
        __syncthreads();
        s[t] += u;
        __syncthreads();
    }
    if (t < nb) g_boffs[t] = s[t] - v;  // exclusive offset for block t
}

__global__ void add_offs() {
    int i = blockIdx.x * blockDim.x + threadIdx.x;
    if (i < NN) g_indptr[i + 1] += g_boffs[i >> 10];
}

__global__ void csr_fill(const int* __restrict__ dst) {
    int e = blockIdx.x * blockDim.x + threadIdx.x;
    if (e < EE) {
        int d = dst[e];
        int p = atomicAdd(&g_cursor[d], 1);
        g_csr[g_indptr[d] + p] = e;
    }
}

__global__ void calc_inv() {
    int b = blockIdx.x * blockDim.x + threadIdx.x;
    if (b < BBATCH) g_inv[b] = 1.0f / fmaxf((float)g_cnt[b], 1.0f);
}

__global__ void vn_init(float* __restrict__ vn, const float* __restrict__ emb) {
    int i = blockIdx.x * blockDim.x + threadIdx.x;
    if (i < BBATCH * HH) vn[i] = emb[i & (HH - 1)];
}

// tf32-round weights once per call (cheap: ~0.8M elements)
__global__ void cvt_w(const float* __restrict__ w, float* __restrict__ o, int n) {
    int i = blockIdx.x * blockDim.x + threadIdx.x;
    if (i < n) o[i] = __uint_as_float(f2tf(w[i]));
}

// ------------------------- node encoder: h = x @ node_W + node_b -------------
__global__ void node_enc(const float* __restrict__ x, const float* __restrict__ W,
                         const float* __restrict__ b, float* __restrict__ h) {
    __shared__ float xs[9];
    int n = blockIdx.x;
    if (threadIdx.x < 9) xs[threadIdx.x] = x[n * 9 + threadIdx.x];
    __syncthreads();
    int c = threadIdx.x;
    float acc = b[c];
#pragma unroll
    for (int k = 0; k < 9; k++) acc += xs[k] * W[k * HH + c];
    h[(size_t)n * HH + c] = acc;
}

// ------------------------- LayerNorm + ReLU (warp per row) -------------------
template <int HD>
__global__ void ln_relu(const float* __restrict__ src, float* __restrict__ dst,
                        const float* __restrict__ g, const float* __restrict__ b) {
    constexpr int PER = HD / 32;
    int warp = (blockIdx.x * blockDim.x + threadIdx.x) >> 5;
    int lane = threadIdx.x & 31;
    if (warp >= NN) return;
    const float* row = src + (size_t)warp * HD;
    float v[PER];
    float s = 0.f, s2 = 0.f;
#pragma unroll
    for (int j = 0; j < PER / 4; j++) {
        float4 t = *(const float4*)(row + j * 128 + lane * 4);
        v[j * 4 + 0] = t.x; v[j * 4 + 1] = t.y; v[j * 4 + 2] = t.z; v[j * 4 + 3] = t.w;
    }
#pragma unroll
    for (int j = 0; j < PER; j++) { s += v[j]; s2 += v[j] * v[j]; }
#pragma unroll
    for (int o = 16; o > 0; o >>= 1) {
        s += __shfl_xor_sync(0xffffffffu, s, o);
        s2 += __shfl_xor_sync(0xffffffffu, s2, o);
    }
    float mu = s / HD;
    float var = s2 / HD - mu * mu;
    float r = rsqrtf(var + 1e-5f);
    float* orow = dst + (size_t)warp * HD;
#pragma unroll
    for (int j = 0; j < PER / 4; j++) {
        float4 o;
        int c = j * 128 + lane * 4;
        o.x = fmaxf((v[j * 4 + 0] - mu) * r * g[c + 0] + b[c + 0], 0.f);
        o.y = fmaxf((v[j * 4 + 1] - mu) * r * g[c + 1] + b[c + 1], 0.f);
        o.z = fmaxf((v[j * 4 + 2] - mu) * r * g[c + 2] + b[c + 2], 0.f);
        o.w = fmaxf((v[j * 4 + 3] - mu) * r * g[c + 3] + b[c + 3], 0.f);
        *(float4*)(orow + c) = o;
    }
}

// ---------- fused: h += vn[batch]; h out; hn = relu(LN(h)) (H=256 only) ------
__global__ void vn_ln_relu(float* __restrict__ h, float* __restrict__ hn,
                           const float* __restrict__ vn, const int* __restrict__ batch,
                           const float* __restrict__ g, const float* __restrict__ b) {
    int warp = (blockIdx.x * blockDim.x + threadIdx.x) >> 5;
    int lane = threadIdx.x & 31;
    if (warp >= NN) return;
    float* row = h + (size_t)warp * HH;
    const float* vrow = vn + ((size_t)batch[warp] << 8);
    float v[8];
    float s = 0.f, s2 = 0.f;
#pragma unroll
    for (int j = 0; j < 2; j++) {
        int c = j * 128 + lane * 4;
        float4 t = *(const float4*)(row + c);
        float4 w = *(const float4*)(vrow + c);
        t.x += w.x; t.y += w.y; t.z += w.z; t.w += w.w;
        *(float4*)(row + c) = t;  // h updated
        v[j * 4 + 0] = t.x; v[j * 4 + 1] = t.y; v[j * 4 + 2] = t.z; v[j * 4 + 3] = t.w;
    }
#pragma unroll
    for (int j = 0; j < 8; j++) { s += v[j]; s2 += v[j] * v[j]; }
#pragma unroll
    for (int o = 16; o > 0; o >>= 1) {
        s += __shfl_xor_sync(0xffffffffu, s, o);
        s2 += __shfl_xor_sync(0xffffffffu, s2, o);
    }
    float mu = s / HH;
    float var = s2 / HH - mu * mu;
    float r = rsqrtf(var + 1e-5f);
    float* orow = hn + (size_t)warp * HH;
#pragma unroll
    for (int j = 0; j < 2; j++) {
        float4 o;
        int c = j * 128 + lane * 4;
        o.x = fmaxf((v[j * 4 + 0] - mu) * r * g[c + 0] + b[c + 0], 0.f);
        o.y = fmaxf((v[j * 4 + 1] - mu) * r * g[c + 1] + b[c + 1], 0.f);
        o.z = fmaxf((v[j * 4 + 2] - mu) * r * g[c + 2] + b[c + 2], 0.f);
        o.w = fmaxf((v[j * 4 + 3] - mu) * r * g[c + 3] + b[c + 3], 0.f);
        *(float4*)(orow + c) = o;
    }
}

// ------------- GENConv aggregation: CSR + online softmax, warp per node ------
__global__ void aggregate(const float* __restrict__ hn, const int* __restrict__ src,
                          const float* __restrict__ eattr, const float* __restrict__ eW,
                          const float* __restrict__ eb, const float* __restrict__ tptr,
                          float* __restrict__ outp) {
    __shared__ float sW[3 * HH];
    __shared__ float sb[HH];
    for (int i = threadIdx.x; i < 3 * HH; i += blockDim.x) sW[i] = eW[i];
    for (int i = threadIdx.x; i < HH; i += blockDim.x) sb[i] = eb[i];
    __syncthreads();
    int warp = blockIdx.x * (blockDim.x >> 5) + (threadIdx.x >> 5);
    int lane = threadIdx.x & 31;
    if (warp >= NN) return;
    float tval = *tptr;
    int e0 = g_indptr[warp], e1 = g_indptr[warp + 1];
    float m[8], d[8], a[8];
#pragma unroll
    for (int j = 0; j < 8; j++) { m[j] = -1e30f; d[j] = 0.f; a[j] = 0.f; }

    for (int e = e0; e < e1; e++) {
        int eid = g_csr[e];
        int u = src[eid];
        float e0a = eattr[eid * 3 + 0];
        float e1a = eattr[eid * 3 + 1];
        float e2a = eattr[eid * 3 + 2];
        const float* hrow = hn + (size_t)u * HH;
#pragma unroll
        for (int gI = 0; gI < 2; gI++) {
            float4 hv = *(const float4*)(hrow + gI * 128 + lane * 4);
            float hvv[4] = {hv.x, hv.y, hv.z, hv.w};
#pragma unroll
            for (int q = 0; q < 4; q++) {
                int c = gI * 128 + lane * 4 + q;
                float ea = sb[c] + e0a * sW[c] + e1a * sW[HH + c] + e2a * sW[2 * HH + c];
                float msg = fmaxf(hvv[q] + ea, 0.f) + 1e-7f;
                float sc = msg * tval;
                int j = gI * 4 + q;
                float mn = fmaxf(m[j], sc);
                float em = __expf(m[j] - mn);
                float es = __expf(sc - mn);
                d[j] = d[j] * em + es;
                a[j] = a[j] * em + msg * es;
                m[j] = mn;
            }
        }
    }
    float* orow = outp + (size_t)warp * HH;
    const float* hnrow = hn + (size_t)warp * HH;
#pragma unroll
    for (int gI = 0; gI < 2; gI++) {
        float4 hv = *(const float4*)(hnrow + gI * 128 + lane * 4);
        float4 o;
        o.x = a[gI * 4 + 0] / (d[gI * 4 + 0] + 1e-16f) + hv.x;
        o.y = a[gI * 4 + 1] / (d[gI * 4 + 1] + 1e-16f) + hv.y;
        o.z = a[gI * 4 + 2] / (d[gI * 4 + 2] + 1e-16f) + hv.z;
        o.w = a[gI * 4 + 3] / (d[gI * 4 + 3] + 1e-16f) + hv.w;
        *(float4*)(orow + gI * 128 + lane * 4) = o;
    }
}

// ------ tf32 mma.sync GEMM, 2-stage cp.async pipeline --------
// C = A[M,K] @ Wc[K,Nc] (+bias, optional +=C). Wc is pre-tf32-rounded.
// BM=BN=128, BK=16, 8 warps, warp tile 32x64.
// As: [m][k] stride 20 (cp.async-filled raw fp32; cvt in register).
// Bs: [k][n] stride 136 (cp.async-filled, already tf32 bits).
__global__ __launch_bounds__(256) void gemm_tf32_pipe(
    const float* __restrict__ A, const float* __restrict__ Wc,
    const float* __restrict__ bias, float* __restrict__ C,
    int M, int K, int Nc, int accum) {
    __shared__ __align__(16) float As[2][128][20];
    __shared__ __align__(16) float Bs[2][16][136];
    int tid = threadIdx.x;
    int lane = tid & 31, warp = tid >> 5;
    int wm = warp >> 1, wn = warp & 1;
    int bm = blockIdx.y * 128, bn = blockIdx.x * 128;

    float acc[2][8][4];
#pragma unroll
    for (int mi = 0; mi < 2; mi++)
#pragma unroll
        for (int ni = 0; ni < 8; ni++)
#pragma unroll
            for (int q = 0; q < 4; q++) acc[mi][ni][q] = 0.f;

    // chunk coords (2 A-chunks + 2 B-chunks per thread per stage)
    int arow0 = tid >> 2, ac4 = tid & 3;          // + p*64 rows
    int bkr0 = tid >> 5, bn4 = tid & 31;          // + p*8 k-rows

    auto load_stage = [&](int st, int k0) {
#pragma unroll
        for (int p = 0; p < 2; p++) {
            int row = arow0 + p * 64;
            int gr = bm + row;
            const float* srcp = A + (size_t)(gr < M ? gr : 0) * K + k0 + ac4 * 4;
            uint32_t dst = (uint32_t)__cvta_generic_to_shared(&As[st][row][ac4 * 4]);
            cp16(dst, srcp, (gr < M) ? 16 : 0);
        }
#pragma unroll
        for (int p = 0; p < 2; p++) {
            int kr = bkr0 + p * 8;
            const float* srcp = Wc + (size_t)(k0 + kr) * Nc + bn + bn4 * 4;
            uint32_t dst = (uint32_t)__cvta_generic_to_shared(&Bs[st][kr][bn4 * 4]);
            cp16(dst, srcp, 16);
        }
    };

    int KT = K >> 4;
    load_stage(0, 0);
    cp_commit();

    for (int kt = 0; kt < KT; kt++) {
        if (kt + 1 < KT) {
            load_stage((kt + 1) & 1, (kt + 1) << 4);
            cp_commit();
            cp_wait<1>();
        } else {
            cp_wait<0>();
        }
        __syncthreads();
        int st = kt & 1;
#pragma unroll
        for (int k8 = 0; k8 < 16; k8 += 8) {
            int kk = k8 + (lane & 3);
            uint32_t af[2][4];
#pragma unroll
            for (int mi = 0; mi < 2; mi++) {
                int mr = wm * 32 + mi * 16 + (lane >> 2);
                af[mi][0] = f2tf(As[st][mr][kk]);
                af[mi][1] = f2tf(As[st][mr + 8][kk]);
                af[mi][2] = f2tf(As[st][mr][kk + 4]);
                af[mi][3] = f2tf(As[st][mr + 8][kk + 4]);
            }
            uint32_t bf[8][2];
#pragma unroll
            for (int ni = 0; ni < 8; ni++) {
                int nc = wn * 64 + ni * 8 + (lane >> 2);
                bf[ni][0] = __float_as_uint(Bs[st][kk][nc]);
                bf[ni][1] = __float_as_uint(Bs[st][kk + 4][nc]);
            }
#pragma unroll
            for (int mi = 0; mi < 2; mi++)
#pragma unroll
                for (int ni = 0; ni < 8; ni++) mma_tf32(acc[mi][ni], af[mi], bf[ni]);
        }
        __syncthreads();
    }
    // epilogue
#pragma unroll
    for (int mi = 0; mi < 2; mi++) {
#pragma unroll
        for (int rr = 0; rr < 2; rr++) {
            int row = bm + wm * 32 + mi * 16 + (lane >> 2) + rr * 8;
            if (row >= M) continue;
#pragma unroll
            for (int ni = 0; ni < 8; ni++) {
                int col = bn + wn * 64 + ni * 8 + (lane & 3) * 2;
                float2 v;
                v.x = acc[mi][ni][rr * 2 + 0] + bias[col];
                v.y = acc[mi][ni][rr * 2 + 1] + bias[col + 1];
                float* p = C + (size_t)row * Nc + col;
                if (accum) { v.x += p[0]; v.y += p[1]; }
                *(float2*)p = v;
            }
        }
    }
}

// ------------- pooling over sorted batch (run-length + few atomics) ----------
__global__ void pool_sum(const float* __restrict__ src, const int* __restrict__ batch,
                         float* __restrict__ out) {
    __shared__ int sb[512];
    int n0 = blockIdx.x * 512;
    int nend = min(n0 + 512, NN);
    for (int i = threadIdx.x; i < nend - n0; i += 256) sb[i] = batch[n0 + i];
    __syncthreads();
    int c = threadIdx.x;
    float acc = 0.f;
    int cur = sb[0];
    for (int n = n0; n < nend; n++) {
        int b = sb[n - n0];
        if (b != cur) {
            atomicAdd(&out[(size_t)cur * HH + c], acc);
            acc = 0.f;
            cur = b;
        }
        acc += src[(size_t)n * HH + c];
    }
    atomicAdd(&out[(size_t)cur * HH + c], acc);
}

__global__ void vn_update(float* __restrict__ vn, const float* __restrict__ vnsum,
                          const float* __restrict__ inv) {
    int i = blockIdx.x * blockDim.x + threadIdx.x;
    if (i < BBATCH * HH) vn[i] += vnsum[i] * inv[i >> 8];
}

__global__ void scale_out(float* __restrict__ out, const float* __restrict__ inv) {
    int i = blockIdx.x * blockDim.x + threadIdx.x;
    if (i < BBATCH * HH) out[i] *= inv[i >> 8];
}

// ------------------------------ host orchestration ---------------------------
extern "C" void kernel_launch(void* const* d_in, const int* in_sizes, int n_in,
                              void* d_out, int out_size) {
    const float* x = (const float*)d_in[0];
    const int* eidx = (const int*)d_in[1];
    const float* eattr = (const float*)d_in[2];
    const int* batch = (const int*)d_in[3];
    const float* node_W = (const float*)d_in[4];
    const float* node_b = (const float*)d_in[5];
    const float* edge_W = (const float*)d_in[6];
    const float* edge_b = (const float*)d_in[7];
    const float* vn_emb = (const float*)d_in[8];
    const float* ln_g = (const float*)d_in[9];
    const float* ln_b = (const float*)d_in[10];
    const float* tt = (const float*)d_in[11];
    const float* W1 = (const float*)d_in[12];
    const float* b1 = (const float*)d_in[13];
    const float* mg = (const float*)d_in[14];
    const float* mb = (const float*)d_in[15];
    const float* W2 = (const float*)d_in[16];
    const float* b2 = (const float*)d_in[17];
    float* out = (float*)d_out;
    const int* srcp = eidx;
    const int* dstp = eidx + EE;

    float *h_, *hn_, *tmp_, *mid_, *vn_, *vnsum_, *inv_, *w1c_, *w2c_;
    cudaGetSymbolAddress((void**)&h_, g_h);
    cudaGetSymbolAddress((void**)&hn_, g_hn);
    cudaGetSymbolAddress((void**)&tmp_, g_tmp);
    cudaGetSymbolAddress((void**)&mid_, g_mid);
    cudaGetSymbolAddress((void**)&vn_, g_vn);
    cudaGetSymbolAddress((void**)&vnsum_, g_vnsum);
    cudaGetSymbolAddress((void**)&inv_, g_inv);
    cudaGetSymbolAddress((void**)&w1c_, g_w1c);
    cudaGetSymbolAddress((void**)&w2c_, g_w2c);

    const int NB_SCAN = (NN + 1023) / 1024;  // 98
    const int NW = 3 * HH * HB2;             // 393216

    // ---- setup: counts, CSR, inv, vn, encoder, weight conversion ----
    zero_setup<<<(NN + 255) / 256, 256>>>();
    count_deg<<<(EE + 255) / 256, 256>>>(dstp);
    count_batch<<<(NN + 255) / 256, 256>>>(batch);
    scan_block<<<NB_SCAN, 1024>>>();
    scan_sums<<<1, 128>>>(NB_SCAN);
    add_offs<<<(NN + 255) / 256, 256>>>();
    csr_fill<<<(EE + 255) / 256, 256>>>(dstp);
    calc_inv<<<(BBATCH + 255) / 256, 256>>>();
    vn_init<<<(BBATCH * HH + 255) / 256, 256>>>(vn_, vn_emb);
    cvt_w<<<(NW + 255) / 256, 256>>>(W1, w1c_, NW);
    cvt_w<<<(NW + 255) / 256, 256>>>(W2, w2c_, NW);
    node_enc<<<NN, 256>>>(x, node_W, node_b, h_);

    // ---- layers 1..3 ----
    for (int l = 1; l < LLAYERS; l++) {
        if (l == 1)
            ln_relu<HH><<<NN / 8, 256>>>(h_, hn_, ln_g + l * HH, ln_b + l * HH);
        else
            vn_ln_relu<<<NN / 8, 256>>>(h_, hn_, vn_, batch, ln_g + l * HH, ln_b + l * HH);
        aggregate<<<NN / 8, 256>>>(hn_, srcp, eattr, edge_W, edge_b, tt + (l - 1), tmp_);
        dim3 g1(HB2 / 128, (NN + 127) / 128);
        gemm_tf32_pipe<<<g1, 256>>>(tmp_, w1c_ + (size_t)(l - 1) * HH * HB2,
                                    b1 + (l - 1) * HB2, mid_, NN, HH, HB2, 0);
        ln_relu<HB2><<<NN / 8, 256>>>(mid_, mid_, mg + (l - 1) * HB2, mb + (l - 1) * HB2);
        dim3 g2(HH / 128, (NN + 127) / 128);
        gemm_tf32_pipe<<<g2, 256>>>(mid_, w2c_ + (size_t)(l - 1) * HB2 * HH,
                                    b2 + (l - 1) * HH, h_, NN, HB2, HH, 1);  // h += MLP out
        zero_f<<<(BBATCH * HH + 255) / 256, 256>>>(vnsum_, BBATCH * HH);
        pool_sum<<<(NN + 511) / 512, 256>>>(h_, batch, vnsum_);
        vn_update<<<(BBATCH * HH + 255) / 256, 256>>>(vn_, vnsum_, inv_);
    }

    // ---- final: h += vn[batch]; norm; mean pool ----
    vn_ln_relu<<<NN / 8, 256>>>(h_, hn_, vn_, batch, ln_g, ln_b);
    zero_f<<<(BBATCH * HH + 255) / 256, 256>>>(out, BBATCH * HH);
    pool_sum<<<(NN + 511) / 512, 256>>>(hn_, batch, out);
    scale_out<<<(BBATCH * HH + 255) / 256, 256>>>(out, inv_);
}

// round 3
// speedup vs baseline: 1.4762x; 1.0727x over previous
#include <cuda_runtime.h>
#include <cstdint>

#define NN 100000
#define EE 200000
#define BBATCH 2048
#define HH 256
#define HB2 512
#define LLAYERS 4

// ------------------------- scratch (device globals; no allocs) ---------------
__device__ float g_h[(size_t)NN * HH];     // node state
__device__ float g_hn[(size_t)NN * HH];    // relu(LN(h))
__device__ float g_tmp[(size_t)NN * HH];   // aggregation output (+residual), tf32-rounded
__device__ float g_mid[(size_t)NN * HB2];  // MLP hidden (tf32-rounded after LN)
__device__ float g_vn[BBATCH * HH];
__device__ float g_vnsum[BBATCH * HH];
__device__ float g_inv[BBATCH];
__device__ float g_w1c[3 * HH * HB2];      // tf32-rounded W1
__device__ float g_w2c[3 * HB2 * HH];      // tf32-rounded W2
__device__ int g_deg[NN];
__device__ int g_indptr[NN + 1];
__device__ int g_cursor[NN];
__device__ int g_csr[EE];
__device__ int g_cnt[BBATCH];
__device__ int g_bsums[128];
__device__ int g_boffs[128];

// ------------------------- small helpers -------------------------------------
__device__ __forceinline__ uint32_t f2tf(float f) {
    uint32_t r;
    asm("cvt.rna.tf32.f32 %0, %1;" : "=r"(r) : "f"(f));
    return r;
}
__device__ __forceinline__ float f2tff(float f) { return __uint_as_float(f2tf(f)); }

__device__ __forceinline__ void mma_tf32(float* c, const uint32_t* a, const uint32_t* b) {
    asm volatile(
        "mma.sync.aligned.m16n8k8.row.col.f32.tf32.tf32.f32 "
        "{%0,%1,%2,%3},{%4,%5,%6,%7},{%8,%9},{%0,%1,%2,%3};"
        : "+f"(c[0]), "+f"(c[1]), "+f"(c[2]), "+f"(c[3])
        : "r"(a[0]), "r"(a[1]), "r"(a[2]), "r"(a[3]), "r"(b[0]), "r"(b[1]));
}

__device__ __forceinline__ void cp16(uint32_t dst, const void* src, int bytes) {
    asm volatile("cp.async.cg.shared.global [%0], [%1], 16, %2;\n" ::"r"(dst), "l"(src),
                 "r"(bytes));
}
__device__ __forceinline__ void cp_commit() { asm volatile("cp.async.commit_group;\n"); }
template <int W>
__device__ __forceinline__ void cp_wait() {
    asm volatile("cp.async.wait_group %0;\n" ::"n"(W));
}

// ------------------------- setup kernels -------------------------------------
__global__ void zero_setup() {
    int i = blockIdx.x * blockDim.x + threadIdx.x;
    if (i < NN) { g_deg[i] = 0; g_cursor[i] = 0; }
    if (i < BBATCH) g_cnt[i] = 0;
}

__global__ void zero_f(float* p, int n) {
    int i = blockIdx.x * blockDim.x + threadIdx.x;
    if (i < n) p[i] = 0.0f;
}

__global__ void count_deg(const int* __restrict__ dst) {
    int e = blockIdx.x * blockDim.x + threadIdx.x;
    if (e < EE) atomicAdd(&g_deg[dst[e]], 1);
}

__global__ void count_batch(const int* __restrict__ batch) {
    int n = blockIdx.x * blockDim.x + threadIdx.x;
    if (n < NN) atomicAdd(&g_cnt[batch[n]], 1);
}

__global__ void scan_block() {  // 98 blocks x 1024
    __shared__ int s[1024];
    int i = blockIdx.x * 1024 + threadIdx.x;
    int v = (i < NN) ? g_deg[i] : 0;
    s[threadIdx.x] = v;
    __syncthreads();
#pragma unroll
    for (int off = 1; off < 1024; off <<= 1) {
        int t = (threadIdx.x >= off) ? s[threadIdx.x - off] : 0;
        __syncthreads();
        s[threadIdx.x] += t;
        __syncthreads();
    }
    if (i < NN) g_indptr[i + 1] = s[threadIdx.x];
    if (threadIdx.x == 1023) g_bsums[blockIdx.x] = s[1023];
    if (i == 0) g_indptr[0] = 0;
}

__global__ void scan_sums(int nb) {  // 1 block x 128
    __shared__ int s[128];
    int t = threadIdx.x;
    int v = (t < nb) ? g_bsums[t] : 0;
    s[t] = v;
    __syncthreads();
#pragma unroll
    for (int off = 1; off < 128; off <<= 1) {
        int u = (t >= off) ? s[t - off] : 0;
        __syncthreads();
        s[t] += u;
        __syncthreads();
    }
    if (t < nb) g_boffs[t] = s[t] - v;  // exclusive offset for block t
}

__global__ void add_offs() {
    int i = blockIdx.x * blockDim.x + threadIdx.x;
    if (i < NN) g_indptr[i + 1] += g_boffs[i >> 10];
}

__global__ void csr_fill(const int* __restrict__ dst) {
    int e = blockIdx.x * blockDim.x + threadIdx.x;
    if (e < EE) {
        int d = dst[e];
        int p = atomicAdd(&g_cursor[d], 1);
        g_csr[g_indptr[d] + p] = e;
    }
}

__global__ void calc_inv() {
    int b = blockIdx.x * blockDim.x + threadIdx.x;
    if (b < BBATCH) g_inv[b] = 1.0f / fmaxf((float)g_cnt[b], 1.0f);
}

__global__ void vn_init(float* __restrict__ vn, const float* __restrict__ emb) {
    int i = blockIdx.x * blockDim.x + threadIdx.x;
    if (i < BBATCH * HH) vn[i] = emb[i & (HH - 1)];
}

// tf32-round weights once per call
__global__ void cvt_w(const float* __restrict__ w, float* __restrict__ o, int n) {
    int i = blockIdx.x * blockDim.x + threadIdx.x;
    if (i < n) o[i] = f2tff(w[i]);
}

// ------------------------- node encoder: h = x @ node_W + node_b -------------
__global__ void node_enc(const float* __restrict__ x, const float* __restrict__ W,
                         const float* __restrict__ b, float* __restrict__ h) {
    __shared__ float xs[9];
    int n = blockIdx.x;
    if (threadIdx.x < 9) xs[threadIdx.x] = x[n * 9 + threadIdx.x];
    __syncthreads();
    int c = threadIdx.x;
    float acc = b[c];
#pragma unroll
    for (int k = 0; k < 9; k++) acc += xs[k] * W[k * HH + c];
    h[(size_t)n * HH + c] = acc;
}

// ---------------- LayerNorm + ReLU (warp per row); optional tf32 rounding ----
template <int HD, bool RND>
__global__ void ln_relu(const float* __restrict__ src, float* __restrict__ dst,
                        const float* __restrict__ g, const float* __restrict__ b) {
    constexpr int PER = HD / 32;
    int warp = (blockIdx.x * blockDim.x + threadIdx.x) >> 5;
    int lane = threadIdx.x & 31;
    if (warp >= NN) return;
    const float* row = src + (size_t)warp * HD;
    float v[PER];
    float s = 0.f, s2 = 0.f;
#pragma unroll
    for (int j = 0; j < PER / 4; j++) {
        float4 t = *(const float4*)(row + j * 128 + lane * 4);
        v[j * 4 + 0] = t.x; v[j * 4 + 1] = t.y; v[j * 4 + 2] = t.z; v[j * 4 + 3] = t.w;
    }
#pragma unroll
    for (int j = 0; j < PER; j++) { s += v[j]; s2 += v[j] * v[j]; }
#pragma unroll
    for (int o = 16; o > 0; o >>= 1) {
        s += __shfl_xor_sync(0xffffffffu, s, o);
        s2 += __shfl_xor_sync(0xffffffffu, s2, o);
    }
    float mu = s / HD;
    float var = s2 / HD - mu * mu;
    float r = rsqrtf(var + 1e-5f);
    float* orow = dst + (size_t)warp * HD;
#pragma unroll
    for (int j = 0; j < PER / 4; j++) {
        float4 o;
        int c = j * 128 + lane * 4;
        o.x = fmaxf((v[j * 4 + 0] - mu) * r * g[c + 0] + b[c + 0], 0.f);
        o.y = fmaxf((v[j * 4 + 1] - mu) * r * g[c + 1] + b[c + 1], 0.f);
        o.z = fmaxf((v[j * 4 + 2] - mu) * r * g[c + 2] + b[c + 2], 0.f);
        o.w = fmaxf((v[j * 4 + 3] - mu) * r * g[c + 3] + b[c + 3], 0.f);
        if (RND) { o.x = f2tff(o.x); o.y = f2tff(o.y); o.z = f2tff(o.z); o.w = f2tff(o.w); }
        *(float4*)(orow + c) = o;
    }
}

// ---------- fused: h += vn[batch]; h out; hn = relu(LN(h)) (H=256 only) ------
__global__ void vn_ln_relu(float* __restrict__ h, float* __restrict__ hn,
                           const float* __restrict__ vn, const int* __restrict__ batch,
                           const float* __restrict__ g, const float* __restrict__ b) {
    int warp = (blockIdx.x * blockDim.x + threadIdx.x) >> 5;
    int lane = threadIdx.x & 31;
    if (warp >= NN) return;
    float* row = h + (size_t)warp * HH;
    const float* vrow = vn + ((size_t)batch[warp] << 8);
    float v[8];
    float s = 0.f, s2 = 0.f;
#pragma unroll
    for (int j = 0; j < 2; j++) {
        int c = j * 128 + lane * 4;
        float4 t = *(const float4*)(row + c);
        float4 w = *(const float4*)(vrow + c);
        t.x += w.x; t.y += w.y; t.z += w.z; t.w += w.w;
        *(float4*)(row + c) = t;  // h updated
        v[j * 4 + 0] = t.x; v[j * 4 + 1] = t.y; v[j * 4 + 2] = t.z; v[j * 4 + 3] = t.w;
    }
#pragma unroll
    for (int j = 0; j < 8; j++) { s += v[j]; s2 += v[j] * v[j]; }
#pragma unroll
    for (int o = 16; o > 0; o >>= 1) {
        s += __shfl_xor_sync(0xffffffffu, s, o);
        s2 += __shfl_xor_sync(0xffffffffu, s2, o);
    }
    float mu = s / HH;
    float var = s2 / HH - mu * mu;
    float r = rsqrtf(var + 1e-5f);
    float* orow = hn + (size_t)warp * HH;
#pragma unroll
    for (int j = 0; j < 2; j++) {
        float4 o;
        int c = j * 128 + lane * 4;
        o.x = fmaxf((v[j * 4 + 0] - mu) * r * g[c + 0] + b[c + 0], 0.f);
        o.y = fmaxf((v[j * 4 + 1] - mu) * r * g[c + 1] + b[c + 1], 0.f);
        o.z = fmaxf((v[j * 4 + 2] - mu) * r * g[c + 2] + b[c + 2], 0.f);
        o.w = fmaxf((v[j * 4 + 3] - mu) * r * g[c + 3] + b[c + 3], 0.f);
        *(float4*)(orow + c) = o;
    }
}

// ------------- GENConv aggregation: CSR + online softmax, warp per node ------
// Output tf32-rounded (consumed only by GEMM1).
__global__ void aggregate(const float* __restrict__ hn, const int* __restrict__ src,
                          const float* __restrict__ eattr, const float* __restrict__ eW,
                          const float* __restrict__ eb, const float* __restrict__ tptr,
                          float* __restrict__ outp) {
    __shared__ float sW[3 * HH];
    __shared__ float sb[HH];
    for (int i = threadIdx.x; i < 3 * HH; i += blockDim.x) sW[i] = eW[i];
    for (int i = threadIdx.x; i < HH; i += blockDim.x) sb[i] = eb[i];
    __syncthreads();
    int warp = blockIdx.x * (blockDim.x >> 5) + (threadIdx.x >> 5);
    int lane = threadIdx.x & 31;
    if (warp >= NN) return;
    float tval = *tptr;
    int e0 = g_indptr[warp], e1 = g_indptr[warp + 1];
    float m[8], d[8], a[8];
#pragma unroll
    for (int j = 0; j < 8; j++) { m[j] = -1e30f; d[j] = 0.f; a[j] = 0.f; }

    for (int e = e0; e < e1; e++) {
        int eid = g_csr[e];
        int u = src[eid];
        float e0a = eattr[eid * 3 + 0];
        float e1a = eattr[eid * 3 + 1];
        float e2a = eattr[eid * 3 + 2];
        const float* hrow = hn + (size_t)u * HH;
#pragma unroll
        for (int gI = 0; gI < 2; gI++) {
            float4 hv = *(const float4*)(hrow + gI * 128 + lane * 4);
            float hvv[4] = {hv.x, hv.y, hv.z, hv.w};
#pragma unroll
            for (int q = 0; q < 4; q++) {
                int c = gI * 128 + lane * 4 + q;
                float ea = sb[c] + e0a * sW[c] + e1a * sW[HH + c] + e2a * sW[2 * HH + c];
                float msg = fmaxf(hvv[q] + ea, 0.f) + 1e-7f;
                float sc = msg * tval;
                int j = gI * 4 + q;
                float mn = fmaxf(m[j], sc);
                float em = __expf(m[j] - mn);
                float es = __expf(sc - mn);
                d[j] = d[j] * em + es;
                a[j] = a[j] * em + msg * es;
                m[j] = mn;
            }
        }
    }
    float* orow = outp + (size_t)warp * HH;
    const float* hnrow = hn + (size_t)warp * HH;
#pragma unroll
    for (int gI = 0; gI < 2; gI++) {
        float4 hv = *(const float4*)(hnrow + gI * 128 + lane * 4);
        float4 o;
        o.x = f2tff(a[gI * 4 + 0] / (d[gI * 4 + 0] + 1e-16f) + hv.x);
        o.y = f2tff(a[gI * 4 + 1] / (d[gI * 4 + 1] + 1e-16f) + hv.y);
        o.z = f2tff(a[gI * 4 + 2] / (d[gI * 4 + 2] + 1e-16f) + hv.z);
        o.w = f2tff(a[gI * 4 + 3] / (d[gI * 4 + 3] + 1e-16f) + hv.w);
        *(float4*)(orow + gI * 128 + lane * 4) = o;
    }
}

// ------ tf32 mma.sync GEMM, 2-stage cp.async pipeline, 64x64 warp tile -------
// C = A[M,K] @ Wc[K,Nc] (+bias, optional +=C). A and Wc hold tf32-rounded bits.
// BM=BN=128, BK=16, 4 warps (128 threads).
// As: [m][k] stride 20.  Bs: [k][n] stride 136.  Both conflict-free.
__global__ __launch_bounds__(128) void gemm_tf32_pipe(
    const float* __restrict__ A, const float* __restrict__ Wc,
    const float* __restrict__ bias, float* __restrict__ C,
    int M, int K, int Nc, int accum) {
    __shared__ __align__(16) uint32_t As[2][128][20];
    __shared__ __align__(16) uint32_t Bs[2][16][136];
    int tid = threadIdx.x;
    int lane = tid & 31, warp = tid >> 5;
    int wm = warp >> 1, wn = warp & 1;
    int bm = blockIdx.y * 128, bn = blockIdx.x * 128;

    float acc[4][8][4];
#pragma unroll
    for (int mi = 0; mi < 4; mi++)
#pragma unroll
        for (int ni = 0; ni < 8; ni++)
#pragma unroll
            for (int q = 0; q < 4; q++) acc[mi][ni][q] = 0.f;

    auto load_stage = [&](int st, int k0) {
#pragma unroll
        for (int p = 0; p < 4; p++) {
            int cid = p * 128 + tid;
            int row = cid >> 2, c4 = cid & 3;
            int gr = bm + row;
            const float* srcp = A + (size_t)(gr < M ? gr : 0) * K + k0 + c4 * 4;
            uint32_t dst = (uint32_t)__cvta_generic_to_shared(&As[st][row][c4 * 4]);
            cp16(dst, srcp, (gr < M) ? 16 : 0);
        }
#pragma unroll
        for (int p = 0; p < 4; p++) {
            int cid = p * 128 + tid;
            int kr = cid >> 5, n4 = cid & 31;
            const float* srcp = Wc + (size_t)(k0 + kr) * Nc + bn + n4 * 4;
            uint32_t dst = (uint32_t)__cvta_generic_to_shared(&Bs[st][kr][n4 * 4]);
            cp16(dst, srcp, 16);
        }
    };

    int KT = K >> 4;
    load_stage(0, 0);
    cp_commit();

    for (int kt = 0; kt < KT; kt++) {
        if (kt + 1 < KT) {
            load_stage((kt + 1) & 1, (kt + 1) << 4);
            cp_commit();
            cp_wait<1>();
        } else {
            cp_wait<0>();
        }
        __syncthreads();
        int st = kt & 1;
#pragma unroll
        for (int k8 = 0; k8 < 16; k8 += 8) {
            int kk = k8 + (lane & 3);
            uint32_t af[4][4];
#pragma unroll
            for (int mi = 0; mi < 4; mi++) {
                int mr = wm * 64 + mi * 16 + (lane >> 2);
                af[mi][0] = As[st][mr][kk];
                af[mi][1] = As[st][mr + 8][kk];
                af[mi][2] = As[st][mr][kk + 4];
                af[mi][3] = As[st][mr + 8][kk + 4];
            }
            uint32_t bf[8][2];
#pragma unroll
            for (int ni = 0; ni < 8; ni++) {
                int nc = wn * 64 + ni * 8 + (lane >> 2);
                bf[ni][0] = Bs[st][kk][nc];
                bf[ni][1] = Bs[st][kk + 4][nc];
            }
#pragma unroll
            for (int mi = 0; mi < 4; mi++)
#pragma unroll
                for (int ni = 0; ni < 8; ni++) mma_tf32(acc[mi][ni], af[mi], bf[ni]);
        }
        __syncthreads();
    }
    // epilogue
#pragma unroll
    for (int mi = 0; mi < 4; mi++) {
#pragma unroll
        for (int rr = 0; rr < 2; rr++) {
            int row = bm + wm * 64 + mi * 16 + (lane >> 2) + rr * 8;
            if (row >= M) continue;
#pragma unroll
            for (int ni = 0; ni < 8; ni++) {
                int col = bn + wn * 64 + ni * 8 + (lane & 3) * 2;
                float2 v;
                v.x = acc[mi][ni][rr * 2 + 0] + bias[col];
                v.y = acc[mi][ni][rr * 2 + 1] + bias[col + 1];
                float* p = C + (size_t)row * Nc + col;
                if (accum) { v.x += p[0]; v.y += p[1]; }
                *(float2*)p = v;
            }
        }
    }
}

// ------------- pooling over sorted batch (run-length + few atomics) ----------
__global__ void pool_sum(const float* __restrict__ src, const int* __restrict__ batch,
                         float* __restrict__ out) {
    __shared__ int sb[512];
    int n0 = blockIdx.x * 512;
    int nend = min(n0 + 512, NN);
    for (int i = threadIdx.x; i < nend - n0; i += 256) sb[i] = batch[n0 + i];
    __syncthreads();
    int c = threadIdx.x;
    float acc = 0.f;
    int cur = sb[0];
    for (int n = n0; n < nend; n++) {
        int b = sb[n - n0];
        if (b != cur) {
            atomicAdd(&out[(size_t)cur * HH + c], acc);
            acc = 0.f;
            cur = b;
        }
        acc += src[(size_t)n * HH + c];
    }
    atomicAdd(&out[(size_t)cur * HH + c], acc);
}

__global__ void vn_update(float* __restrict__ vn, const float* __restrict__ vnsum,
                          const float* __restrict__ inv) {
    int i = blockIdx.x * blockDim.x + threadIdx.x;
    if (i < BBATCH * HH) vn[i] += vnsum[i] * inv[i >> 8];
}

__global__ void scale_out(float* __restrict__ out, const float* __restrict__ inv) {
    int i = blockIdx.x * blockDim.x + threadIdx.x;
    if (i < BBATCH * HH) out[i] *= inv[i >> 8];
}

// ------------------------------ host orchestration ---------------------------
extern "C" void kernel_launch(void* const* d_in, const int* in_sizes, int n_in,
                              void* d_out, int out_size) {
    const float* x = (const float*)d_in[0];
    const int* eidx = (const int*)d_in[1];
    const float* eattr = (const float*)d_in[2];
    const int* batch = (const int*)d_in[3];
    const float* node_W = (const float*)d_in[4];
    const float* node_b = (const float*)d_in[5];
    const float* edge_W = (const float*)d_in[6];
    const float* edge_b = (const float*)d_in[7];
    const float* vn_emb = (const float*)d_in[8];
    const float* ln_g = (const float*)d_in[9];
    const float* ln_b = (const float*)d_in[10];
    const float* tt = (const float*)d_in[11];
    const float* W1 = (const float*)d_in[12];
    const float* b1 = (const float*)d_in[13];
    const float* mg = (const float*)d_in[14];
    const float* mb = (const float*)d_in[15];
    const float* W2 = (const float*)d_in[16];
    const float* b2 = (const float*)d_in[17];
    float* out = (float*)d_out;
    const int* srcp = eidx;
    const int* dstp = eidx + EE;

    float *h_, *hn_, *tmp_, *mid_, *vn_, *vnsum_, *inv_, *w1c_, *w2c_;
    cudaGetSymbolAddress((void**)&h_, g_h);
    cudaGetSymbolAddress((void**)&hn_, g_hn);
    cudaGetSymbolAddress((void**)&tmp_, g_tmp);
    cudaGetSymbolAddress((void**)&mid_, g_mid);
    cudaGetSymbolAddress((void**)&vn_, g_vn);
    cudaGetSymbolAddress((void**)&vnsum_, g_vnsum);
    cudaGetSymbolAddress((void**)&inv_, g_inv);
    cudaGetSymbolAddress((void**)&w1c_, g_w1c);
    cudaGetSymbolAddress((void**)&w2c_, g_w2c);

    const int NB_SCAN = (NN + 1023) / 1024;  // 98
    const int NW = 3 * HH * HB2;             // 393216

    // ---- setup: counts, CSR, inv, vn, encoder, weight conversion ----
    zero_setup<<<(NN + 255) / 256, 256>>>();
    count_deg<<<(EE + 255) / 256, 256>>>(dstp);
    count_batch<<<(NN + 255) / 256, 256>>>(batch);
    scan_block<<<NB_SCAN, 1024>>>();
    scan_sums<<<1, 128>>>(NB_SCAN);
    add_offs<<<(NN + 255) / 256, 256>>>();
    csr_fill<<<(EE + 255) / 256, 256>>>(dstp);
    calc_inv<<<(BBATCH + 255) / 256, 256>>>();
    vn_init<<<(BBATCH * HH + 255) / 256, 256>>>(vn_, vn_emb);
    cvt_w<<<(NW + 255) / 256, 256>>>(W1, w1c_, NW);
    cvt_w<<<(NW + 255) / 256, 256>>>(W2, w2c_, NW);
    node_enc<<<NN, 256>>>(x, node_W, node_b, h_);

    // ---- layers 1..3 ----
    for (int l = 1; l < LLAYERS; l++) {
        if (l == 1)
            ln_relu<HH, false><<<NN / 8, 256>>>(h_, hn_, ln_g + l * HH, ln_b + l * HH);
        else
            vn_ln_relu<<<NN / 8, 256>>>(h_, hn_, vn_, batch, ln_g + l * HH, ln_b + l * HH);
        aggregate<<<NN / 8, 256>>>(hn_, srcp, eattr, edge_W, edge_b, tt + (l - 1), tmp_);
        dim3 g1(HB2 / 128, (NN + 127) / 128);
        gemm_tf32_pipe<<<g1, 128>>>(tmp_, w1c_ + (size_t)(l - 1) * HH * HB2,
                                    b1 + (l - 1) * HB2, mid_, NN, HH, HB2, 0);
        ln_relu<HB2, true><<<NN / 8, 256>>>(mid_, mid_, mg + (l - 1) * HB2, mb + (l - 1) * HB2);
        dim3 g2(HH / 128, (NN + 127) / 128);
        gemm_tf32_pipe<<<g2, 128>>>(mid_, w2c_ + (size_t)(l - 1) * HB2 * HH,
                                    b2 + (l - 1) * HH, h_, NN, HB2, HH, 1);  // h += MLP out
        zero_f<<<(BBATCH * HH + 255) / 256, 256>>>(vnsum_, BBATCH * HH);
        pool_sum<<<(NN + 511) / 512, 256>>>(h_, batch, vnsum_);
        vn_update<<<(BBATCH * HH + 255) / 256, 256>>>(vn_, vnsum_, inv_);
    }

    // ---- final: h += vn[batch]; norm; mean pool ----
    vn_ln_relu<<<NN / 8, 256>>>(h_, hn_, vn_, batch, ln_g, ln_b);
    zero_f<<<(BBATCH * HH + 255) / 256, 256>>>(out, BBATCH * HH);
    pool_sum<<<(NN + 511) / 512, 256>>>(hn_, batch, out);
    scale_out<<<(BBATCH * HH + 255) / 256, 256>>>(out, inv_);
}

// round 4
// speedup vs baseline: 1.4991x; 1.0155x over previous
#include <cuda_runtime.h>
#include <cstdint>

#define NN 100000
#define EE 200000
#define BBATCH 2048
#define HH 256
#define HB2 512
#define LLAYERS 4

// ------------------------- scratch (device globals; no allocs) ---------------
__device__ float g_h[(size_t)NN * HH];
__device__ float g_hn[(size_t)NN * HH];
__device__ float g_tmp[(size_t)NN * HH];
__device__ float g_mid[(size_t)NN * HB2];
__device__ float g_vn[BBATCH * HH];
__device__ float g_vnsum[BBATCH * HH];
__device__ float g_inv[BBATCH];
__device__ float g_w1c[3 * HH * HB2];
__device__ float g_w2c[3 * HB2 * HH];
__device__ int g_deg[NN];
__device__ int g_indptr[NN + 1];
__device__ int g_cursor[NN];
__device__ int g_csr[EE];
__device__ int g_cnt[BBATCH];
__device__ int g_bsums[128];
__device__ int g_boffs[128];

// ------------------------- small helpers -------------------------------------
__device__ __forceinline__ uint32_t f2tf(float f) {
    uint32_t r;
    asm("cvt.rna.tf32.f32 %0, %1;" : "=r"(r) : "f"(f));
    return r;
}
__device__ __forceinline__ float f2tff(float f) { return __uint_as_float(f2tf(f)); }

__device__ __forceinline__ void mma_tf32(float* c, const uint32_t* a, const uint32_t* b) {
    asm volatile(
        "mma.sync.aligned.m16n8k8.row.col.f32.tf32.tf32.f32 "
        "{%0,%1,%2,%3},{%4,%5,%6,%7},{%8,%9},{%0,%1,%2,%3};"
        : "+f"(c[0]), "+f"(c[1]), "+f"(c[2]), "+f"(c[3])
        : "r"(a[0]), "r"(a[1]), "r"(a[2]), "r"(a[3]), "r"(b[0]), "r"(b[1]));
}

__device__ __forceinline__ void cp16(uint32_t dst, const void* src, int bytes) {
    asm volatile("cp.async.cg.shared.global [%0], [%1], 16, %2;\n" ::"r"(dst), "l"(src),
                 "r"(bytes));
}
__device__ __forceinline__ void cp_commit() { asm volatile("cp.async.commit_group;\n"); }
template <int W>
__device__ __forceinline__ void cp_wait() {
    asm volatile("cp.async.wait_group %0;\n" ::"n"(W));
}

// ------------------------- setup kernels -------------------------------------
__global__ void zero_setup() {
    int i = blockIdx.x * blockDim.x + threadIdx.x;
    if (i < NN) { g_deg[i] = 0; g_cursor[i] = 0; }
    if (i < BBATCH) g_cnt[i] = 0;
}

__global__ void zero_f(float* p, int n) {
    int i = blockIdx.x * blockDim.x + threadIdx.x;
    if (i < n) p[i] = 0.0f;
}

__global__ void count_deg(const int* __restrict__ dst) {
    int e = blockIdx.x * blockDim.x + threadIdx.x;
    if (e < EE) atomicAdd(&g_deg[dst[e]], 1);
}

__global__ void count_batch(const int* __restrict__ batch) {
    int n = blockIdx.x * blockDim.x + threadIdx.x;
    if (n < NN) atomicAdd(&g_cnt[batch[n]], 1);
}

__global__ void scan_block() {
    __shared__ int s[1024];
    int i = blockIdx.x * 1024 + threadIdx.x;
    int v = (i < NN) ? g_deg[i] : 0;
    s[threadIdx.x] = v;
    __syncthreads();
#pragma unroll
    for (int off = 1; off < 1024; off <<= 1) {
        int t = (threadIdx.x >= off) ? s[threadIdx.x - off] : 0;
        __syncthreads();
        s[threadIdx.x] += t;
        __syncthreads();
    }
    if (i < NN) g_indptr[i + 1] = s[threadIdx.x];
    if (threadIdx.x == 1023) g_bsums[blockIdx.x] = s[1023];
    if (i == 0) g_indptr[0] = 0;
}

__global__ void scan_sums(int nb) {
    __shared__ int s[128];
    int t = threadIdx.x;
    int v = (t < nb) ? g_bsums[t] : 0;
    s[t] = v;
    __syncthreads();
#pragma unroll
    for (int off = 1; off < 128; off <<= 1) {
        int u = (t >= off) ? s[t - off] : 0;
        __syncthreads();
        s[t] += u;
        __syncthreads();
    }
    if (t < nb) g_boffs[t] = s[t] - v;
}

__global__ void add_offs() {
    int i = blockIdx.x * blockDim.x + threadIdx.x;
    if (i < NN) g_indptr[i + 1] += g_boffs[i >> 10];
}

__global__ void csr_fill(const int* __restrict__ dst) {
    int e = blockIdx.x * blockDim.x + threadIdx.x;
    if (e < EE) {
        int d = dst[e];
        int p = atomicAdd(&g_cursor[d], 1);
        g_csr[g_indptr[d] + p] = e;
    }
}

__global__ void calc_inv() {
    int b = blockIdx.x * blockDim.x + threadIdx.x;
    if (b < BBATCH) g_inv[b] = 1.0f / fmaxf((float)g_cnt[b], 1.0f);
}

__global__ void vn_init(float* __restrict__ vn, const float* __restrict__ emb) {
    int i = blockIdx.x * blockDim.x + threadIdx.x;
    if (i < BBATCH * HH) vn[i] = emb[i & (HH - 1)];
}

__global__ void cvt_w(const float* __restrict__ w, float* __restrict__ o, int n) {
    int i = blockIdx.x * blockDim.x + threadIdx.x;
    if (i < n) o[i] = f2tff(w[i]);
}

// ------------------------- node encoder -------------------------------------
__global__ void node_enc(const float* __restrict__ x, const float* __restrict__ W,
                         const float* __restrict__ b, float* __restrict__ h) {
    __shared__ float xs[9];
    int n = blockIdx.x;
    if (threadIdx.x < 9) xs[threadIdx.x] = x[n * 9 + threadIdx.x];
    __syncthreads();
    int c = threadIdx.x;
    float acc = b[c];
#pragma unroll
    for (int k = 0; k < 9; k++) acc += xs[k] * W[k * HH + c];
    h[(size_t)n * HH + c] = acc;
}

// ---------------- LayerNorm + ReLU (warp per row) ----------------------------
template <int HD, bool RND>
__global__ void ln_relu(const float* __restrict__ src, float* __restrict__ dst,
                        const float* __restrict__ g, const float* __restrict__ b) {
    constexpr int PER = HD / 32;
    int warp = (blockIdx.x * blockDim.x + threadIdx.x) >> 5;
    int lane = threadIdx.x & 31;
    if (warp >= NN) return;
    const float* row = src + (size_t)warp * HD;
    float v[PER];
    float s = 0.f, s2 = 0.f;
#pragma unroll
    for (int j = 0; j < PER / 4; j++) {
        float4 t = *(const float4*)(row + j * 128 + lane * 4);
        v[j * 4 + 0] = t.x; v[j * 4 + 1] = t.y; v[j * 4 + 2] = t.z; v[j * 4 + 3] = t.w;
    }
#pragma unroll
    for (int j = 0; j < PER; j++) { s += v[j]; s2 += v[j] * v[j]; }
#pragma unroll
    for (int o = 16; o > 0; o >>= 1) {
        s += __shfl_xor_sync(0xffffffffu, s, o);
        s2 += __shfl_xor_sync(0xffffffffu, s2, o);
    }
    float mu = s / HD;
    float var = s2 / HD - mu * mu;
    float r = rsqrtf(var + 1e-5f);
    float* orow = dst + (size_t)warp * HD;
#pragma unroll
    for (int j = 0; j < PER / 4; j++) {
        float4 o;
        int c = j * 128 + lane * 4;
        o.x = fmaxf((v[j * 4 + 0] - mu) * r * g[c + 0] + b[c + 0], 0.f);
        o.y = fmaxf((v[j * 4 + 1] - mu) * r * g[c + 1] + b[c + 1], 0.f);
        o.z = fmaxf((v[j * 4 + 2] - mu) * r * g[c + 2] + b[c + 2], 0.f);
        o.w = fmaxf((v[j * 4 + 3] - mu) * r * g[c + 3] + b[c + 3], 0.f);
        if (RND) { o.x = f2tff(o.x); o.y = f2tff(o.y); o.z = f2tff(o.z); o.w = f2tff(o.w); }
        *(float4*)(orow + c) = o;
    }
}

// ---------- fused: h += vn[batch]; hn = relu(LN(h)) --------------------------
__global__ void vn_ln_relu(float* __restrict__ h, float* __restrict__ hn,
                           const float* __restrict__ vn, const int* __restrict__ batch,
                           const float* __restrict__ g, const float* __restrict__ b) {
    int warp = (blockIdx.x * blockDim.x + threadIdx.x) >> 5;
    int lane = threadIdx.x & 31;
    if (warp >= NN) return;
    float* row = h + (size_t)warp * HH;
    const float* vrow = vn + ((size_t)batch[warp] << 8);
    float v[8];
    float s = 0.f, s2 = 0.f;
#pragma unroll
    for (int j = 0; j < 2; j++) {
        int c = j * 128 + lane * 4;
        float4 t = *(const float4*)(row + c);
        float4 w = *(const float4*)(vrow + c);
        t.x += w.x; t.y += w.y; t.z += w.z; t.w += w.w;
        *(float4*)(row + c) = t;
        v[j * 4 + 0] = t.x; v[j * 4 + 1] = t.y; v[j * 4 + 2] = t.z; v[j * 4 + 3] = t.w;
    }
#pragma unroll
    for (int j = 0; j < 8; j++) { s += v[j]; s2 += v[j] * v[j]; }
#pragma unroll
    for (int o = 16; o > 0; o >>= 1) {
        s += __shfl_xor_sync(0xffffffffu, s, o);
        s2 += __shfl_xor_sync(0xffffffffu, s2, o);
    }
    float mu = s / HH;
    float var = s2 / HH - mu * mu;
    float r = rsqrtf(var + 1e-5f);
    float* orow = hn + (size_t)warp * HH;
#pragma unroll
    for (int j = 0; j < 2; j++) {
        float4 o;
        int c = j * 128 + lane * 4;
        o.x = fmaxf((v[j * 4 + 0] - mu) * r * g[c + 0] + b[c + 0], 0.f);
        o.y = fmaxf((v[j * 4 + 1] - mu) * r * g[c + 1] + b[c + 1], 0.f);
        o.z = fmaxf((v[j * 4 + 2] - mu) * r * g[c + 2] + b[c + 2], 0.f);
        o.w = fmaxf((v[j * 4 + 3] - mu) * r * g[c + 3] + b[c + 3], 0.f);
        *(float4*)(orow + c) = o;
    }
}

// ------------- GENConv aggregation: CSR + online softmax ---------------------
__global__ void aggregate(const float* __restrict__ hn, const int* __restrict__ src,
                          const float* __restrict__ eattr, const float* __restrict__ eW,
                          const float* __restrict__ eb, const float* __restrict__ tptr,
                          float* __restrict__ outp) {
    __shared__ float sW[3 * HH];
    __shared__ float sb[HH];
    for (int i = threadIdx.x; i < 3 * HH; i += blockDim.x) sW[i] = eW[i];
    for (int i = threadIdx.x; i < HH; i += blockDim.x) sb[i] = eb[i];
    __syncthreads();
    int warp = blockIdx.x * (blockDim.x >> 5) + (threadIdx.x >> 5);
    int lane = threadIdx.x & 31;
    if (warp >= NN) return;
    float tval = *tptr;
    int e0 = g_indptr[warp], e1 = g_indptr[warp + 1];
    float m[8], d[8], a[8];
#pragma unroll
    for (int j = 0; j < 8; j++) { m[j] = -1e30f; d[j] = 0.f; a[j] = 0.f; }

    for (int e = e0; e < e1; e++) {
        int eid = g_csr[e];
        int u = src[eid];
        float e0a = eattr[eid * 3 + 0];
        float e1a = eattr[eid * 3 + 1];
        float e2a = eattr[eid * 3 + 2];
        const float* hrow = hn + (size_t)u * HH;
#pragma unroll
        for (int gI = 0; gI < 2; gI++) {
            float4 hv = *(const float4*)(hrow + gI * 128 + lane * 4);
            float hvv[4] = {hv.x, hv.y, hv.z, hv.w};
#pragma unroll
            for (int q = 0; q < 4; q++) {
                int c = gI * 128 + lane * 4 + q;
                float ea = sb[c] + e0a * sW[c] + e1a * sW[HH + c] + e2a * sW[2 * HH + c];
                float msg = fmaxf(hvv[q] + ea, 0.f) + 1e-7f;
                float sc = msg * tval;
                int j = gI * 4 + q;
                float mn = fmaxf(m[j], sc);
                float em = __expf(m[j] - mn);
                float es = __expf(sc - mn);
                d[j] = d[j] * em + es;
                a[j] = a[j] * em + msg * es;
                m[j] = mn;
            }
        }
    }
    float* orow = outp + (size_t)warp * HH;
    const float* hnrow = hn + (size_t)warp * HH;
#pragma unroll
    for (int gI = 0; gI < 2; gI++) {
        float4 hv = *(const float4*)(hnrow + gI * 128 + lane * 4);
        float4 o;
        o.x = f2tff(a[gI * 4 + 0] / (d[gI * 4 + 0] + 1e-16f) + hv.x);
        o.y = f2tff(a[gI * 4 + 1] / (d[gI * 4 + 1] + 1e-16f) + hv.y);
        o.z = f2tff(a[gI * 4 + 2] / (d[gI * 4 + 2] + 1e-16f) + hv.z);
        o.w = f2tff(a[gI * 4 + 3] / (d[gI * 4 + 3] + 1e-16f) + hv.w);
        *(float4*)(orow + gI * 128 + lane * 4) = o;
    }
}

// ------ GEMM1 fused with LayerNorm+ReLU+tf32-round epilogue ------------------
// mid = round_tf32(relu(LN(A @ W1 + b1)))  ;  A[M,256] tf32 bits, W1[256,512].
// BM=64, BN=512 (full row), BK=16, 8 warps, warp tile 64x64 (wn=warp).
// Dynamic smem: As[2][64][20] u32 (10240B) + Bs[2][16][520] u32 (66560B).
__global__ __launch_bounds__(256) void gemm1_ln(
    const float* __restrict__ A, const float* __restrict__ Wc,
    const float* __restrict__ bias, const float* __restrict__ gam,
    const float* __restrict__ bet, float* __restrict__ mid, int M) {
    extern __shared__ char smraw[];
    typedef uint32_t AsT[64][20];
    typedef uint32_t BsT[16][520];
    AsT* As = (AsT*)smraw;
    BsT* Bs = (BsT*)(smraw + 2 * sizeof(AsT));
    const int K = HH, Nc = HB2, KT = K >> 4;

    int tid = threadIdx.x;
    int lane = tid & 31, warp = tid >> 5;
    int wn = warp;
    int bm = blockIdx.x * 64;

    float acc[4][8][4];
#pragma unroll
    for (int mi = 0; mi < 4; mi++)
#pragma unroll
        for (int ni = 0; ni < 8; ni++)
#pragma unroll
            for (int q = 0; q < 4; q++) acc[mi][ni][q] = 0.f;

    auto load_stage = [&](int st, int k0) {
        {
            int row = tid >> 2, c4 = tid & 3;
            int gr = bm + row;
            const float* srcp = A + (size_t)(gr < M ? gr : 0) * K + k0 + c4 * 4;
            uint32_t dst = (uint32_t)__cvta_generic_to_shared(&As[st][row][c4 * 4]);
            cp16(dst, srcp, (gr < M) ? 16 : 0);
        }
#pragma unroll
        for (int p = 0; p < 8; p++) {
            int cid = p * 256 + tid;
            int kr = cid >> 7, n4 = cid & 127;
            const float* srcp = Wc + (size_t)(k0 + kr) * Nc + n4 * 4;
            uint32_t dst = (uint32_t)__cvta_generic_to_shared(&Bs[st][kr][n4 * 4]);
            cp16(dst, srcp, 16);
        }
    };

    load_stage(0, 0);
    cp_commit();

    for (int kt = 0; kt < KT; kt++) {
        if (kt + 1 < KT) {
            load_stage((kt + 1) & 1, (kt + 1) << 4);
            cp_commit();
            cp_wait<1>();
        } else {
            cp_wait<0>();
        }
        __syncthreads();
        int st = kt & 1;
#pragma unroll
        for (int k8 = 0; k8 < 16; k8 += 8) {
            int kk = k8 + (lane & 3);
            uint32_t af[4][4];
#pragma unroll
            for (int mi = 0; mi < 4; mi++) {
                int mr = mi * 16 + (lane >> 2);
                af[mi][0] = As[st][mr][kk];
                af[mi][1] = As[st][mr + 8][kk];
                af[mi][2] = As[st][mr][kk + 4];
                af[mi][3] = As[st][mr + 8][kk + 4];
            }
            uint32_t bf[8][2];
#pragma unroll
            for (int ni = 0; ni < 8; ni++) {
                int nc = wn * 64 + ni * 8 + (lane >> 2);
                bf[ni][0] = Bs[st][kk][nc];
                bf[ni][1] = Bs[st][kk + 4][nc];
            }
#pragma unroll
            for (int mi = 0; mi < 4; mi++)
#pragma unroll
                for (int ni = 0; ni < 8; ni++) mma_tf32(acc[mi][ni], af[mi], bf[ni]);
        }
        __syncthreads();
    }

    // ---- epilogue: bias + row LayerNorm + ReLU + tf32 round ----
    float* swsum = (float*)smraw;          // [8][64]
    float* swsq = swsum + 512;             // [8][64]
    float* smu = swsum + 1024;             // [64]
    float* srv = swsum + 1088;             // [64]
    float* sbias = (float*)(smraw + 2 * sizeof(AsT));  // [512]
    float* sgam = sbias + 512;
    float* sbet = sbias + 1024;
    for (int i = tid; i < 512; i += 256) {
        sbias[i] = bias[i];
        sgam[i] = gam[i];
        sbet[i] = bet[i];
    }
    __syncthreads();

    float psum[8], psq[8];
#pragma unroll
    for (int mi = 0; mi < 4; mi++)
#pragma unroll
        for (int rr = 0; rr < 2; rr++) {
            int sidx = mi * 2 + rr;
            float s = 0.f, q2s = 0.f;
#pragma unroll
            for (int ni = 0; ni < 8; ni++)
#pragma unroll
                for (int q2 = 0; q2 < 2; q2++) {
                    int col = wn * 64 + ni * 8 + (lane & 3) * 2 + q2;
                    float v = acc[mi][ni][rr * 2 + q2] + sbias[col];
                    s += v;
                    q2s += v * v;
                }
            psum[sidx] = s;
            psq[sidx] = q2s;
        }
#pragma unroll
    for (int sidx = 0; sidx < 8; sidx++) {
        psum[sidx] += __shfl_xor_sync(0xffffffffu, psum[sidx], 1);
        psum[sidx] += __shfl_xor_sync(0xffffffffu, psum[sidx], 2);
        psq[sidx] += __shfl_xor_sync(0xffffffffu, psq[sidx], 1);
        psq[sidx] += __shfl_xor_sync(0xffffffffu, psq[sidx], 2);
    }
    if ((lane & 3) == 0) {
#pragma unroll
        for (int mi = 0; mi < 4; mi++)
#pragma unroll
            for (int rr = 0; rr < 2; rr++) {
                int row = mi * 16 + (lane >> 2) + rr * 8;
                swsum[warp * 64 + row] = psum[mi * 2 + rr];
                swsq[warp * 64 + row] = psq[mi * 2 + rr];
            }
    }
    __syncthreads();
    if (tid < 64) {
        float s = 0.f, q = 0.f;
#pragma unroll
        for (int w = 0; w < 8; w++) { s += swsum[w * 64 + tid]; q += swsq[w * 64 + tid]; }
        float mu = s * (1.0f / HB2);
        float var = q * (1.0f / HB2) - mu * mu;
        smu[tid] = mu;
        srv[tid] = rsqrtf(var + 1e-5f);
    }
    __syncthreads();

#pragma unroll
    for (int mi = 0; mi < 4; mi++)
#pragma unroll
        for (int rr = 0; rr < 2; rr++) {
            int row = mi * 16 + (lane >> 2) + rr * 8;
            int grow = bm + row;
            if (grow >= M) continue;
            float mu = smu[row], rv = srv[row];
            float* orow = mid + (size_t)grow * HB2;
#pragma unroll
            for (int ni = 0; ni < 8; ni++) {
                int col = wn * 64 + ni * 8 + (lane & 3) * 2;
                float2 o;
                float v0 = acc[mi][ni][rr * 2 + 0] + sbias[col];
                float v1 = acc[mi][ni][rr * 2 + 1] + sbias[col + 1];
                o.x = f2tff(fmaxf((v0 - mu) * rv * sgam[col] + sbet[col], 0.f));
                o.y = f2tff(fmaxf((v1 - mu) * rv * sgam[col + 1] + sbet[col + 1], 0.f));
                *(float2*)(orow + col) = o;
            }
        }
}

// ------ generic tf32 GEMM (used for GEMM2), 2-stage cp.async -----------------
__global__ __launch_bounds__(128) void gemm_tf32_pipe(
    const float* __restrict__ A, const float* __restrict__ Wc,
    const float* __restrict__ bias, float* __restrict__ C,
    int M, int K, int Nc, int accum) {
    __shared__ __align__(16) uint32_t As[2][128][20];
    __shared__ __align__(16) uint32_t Bs[2][16][136];
    int tid = threadIdx.x;
    int lane = tid & 31, warp = tid >> 5;
    int wm = warp >> 1, wn = warp & 1;
    int bm = blockIdx.y * 128, bn = blockIdx.x * 128;

    float acc[4][8][4];
#pragma unroll
    for (int mi = 0; mi < 4; mi++)
#pragma unroll
        for (int ni = 0; ni < 8; ni++)
#pragma unroll
            for (int q = 0; q < 4; q++) acc[mi][ni][q] = 0.f;

    auto load_stage = [&](int st, int k0) {
#pragma unroll
        for (int p = 0; p < 4; p++) {
            int cid = p * 128 + tid;
            int row = cid >> 2, c4 = cid & 3;
            int gr = bm + row;
            const float* srcp = A + (size_t)(gr < M ? gr : 0) * K + k0 + c4 * 4;
            uint32_t dst = (uint32_t)__cvta_generic_to_shared(&As[st][row][c4 * 4]);
            cp16(dst, srcp, (gr < M) ? 16 : 0);
        }
#pragma unroll
        for (int p = 0; p < 4; p++) {
            int cid = p * 128 + tid;
            int kr = cid >> 5, n4 = cid & 31;
            const float* srcp = Wc + (size_t)(k0 + kr) * Nc + bn + n4 * 4;
            uint32_t dst = (uint32_t)__cvta_generic_to_shared(&Bs[st][kr][n4 * 4]);
            cp16(dst, srcp, 16);
        }
    };

    int KT = K >> 4;
    load_stage(0, 0);
    cp_commit();

    for (int kt = 0; kt < KT; kt++) {
        if (kt + 1 < KT) {
            load_stage((kt + 1) & 1, (kt + 1) << 4);
            cp_commit();
            cp_wait<1>();
        } else {
            cp_wait<0>();
        }
        __syncthreads();
        int st = kt & 1;
#pragma unroll
        for (int k8 = 0; k8 < 16; k8 += 8) {
            int kk = k8 + (lane & 3);
            uint32_t af[4][4];
#pragma unroll
            for (int mi = 0; mi < 4; mi++) {
                int mr = wm * 64 + mi * 16 + (lane >> 2);
                af[mi][0] = As[st][mr][kk];
                af[mi][1] = As[st][mr + 8][kk];
                af[mi][2] = As[st][mr][kk + 4];
                af[mi][3] = As[st][mr + 8][kk + 4];
            }
            uint32_t bf[8][2];
#pragma unroll
            for (int ni = 0; ni < 8; ni++) {
                int nc = wn * 64 + ni * 8 + (lane >> 2);
                bf[ni][0] = Bs[st][kk][nc];
                bf[ni][1] = Bs[st][kk + 4][nc];
            }
#pragma unroll
            for (int mi = 0; mi < 4; mi++)
#pragma unroll
                for (int ni = 0; ni < 8; ni++) mma_tf32(acc[mi][ni], af[mi], bf[ni]);
        }
        __syncthreads();
    }
#pragma unroll
    for (int mi = 0; mi < 4; mi++) {
#pragma unroll
        for (int rr = 0; rr < 2; rr++) {
            int row = bm + wm * 64 + mi * 16 + (lane >> 2) + rr * 8;
            if (row >= M) continue;
#pragma unroll
            for (int ni = 0; ni < 8; ni++) {
                int col = bn + wn * 64 + ni * 8 + (lane & 3) * 2;
                float2 v;
                v.x = acc[mi][ni][rr * 2 + 0] + bias[col];
                v.y = acc[mi][ni][rr * 2 + 1] + bias[col + 1];
                float* p = C + (size_t)row * Nc + col;
                if (accum) { v.x += p[0]; v.y += p[1]; }
                *(float2*)p = v;
            }
        }
    }
}

// ------------- pooling over sorted batch -------------------------------------
__global__ void pool_sum(const float* __restrict__ src, const int* __restrict__ batch,
                         float* __restrict__ out) {
    __shared__ int sb[512];
    int n0 = blockIdx.x * 512;
    int nend = min(n0 + 512, NN);
    for (int i = threadIdx.x; i < nend - n0; i += 256) sb[i] = batch[n0 + i];
    __syncthreads();
    int c = threadIdx.x;
    float acc = 0.f;
    int cur = sb[0];
    for (int n = n0; n < nend; n++) {
        int b = sb[n - n0];
        if (b != cur) {
            atomicAdd(&out[(size_t)cur * HH + c], acc);
            acc = 0.f;
            cur = b;
        }
        acc += src[(size_t)n * HH + c];
    }
    atomicAdd(&out[(size_t)cur * HH + c], acc);
}

__global__ void vn_update(float* __restrict__ vn, const float* __restrict__ vnsum,
                          const float* __restrict__ inv) {
    int i = blockIdx.x * blockDim.x + threadIdx.x;
    if (i < BBATCH * HH) vn[i] += vnsum[i] * inv[i >> 8];
}

__global__ void scale_out(float* __restrict__ out, const float* __restrict__ inv) {
    int i = blockIdx.x * blockDim.x + threadIdx.x;
    if (i < BBATCH * HH) out[i] *= inv[i >> 8];
}

// ------------------------------ host orchestration ---------------------------
extern "C" void kernel_launch(void* const* d_in, const int* in_sizes, int n_in,
                              void* d_out, int out_size) {
    const float* x = (const float*)d_in[0];
    const int* eidx = (const int*)d_in[1];
    const float* eattr = (const float*)d_in[2];
    const int* batch = (const int*)d_in[3];
    const float* node_W = (const float*)d_in[4];
    const float* node_b = (const float*)d_in[5];
    const float* edge_W = (const float*)d_in[6];
    const float* edge_b = (const float*)d_in[7];
    const float* vn_emb = (const float*)d_in[8];
    const float* ln_g = (const float*)d_in[9];
    const float* ln_b = (const float*)d_in[10];
    const float* tt = (const float*)d_in[11];
    const float* W1 = (const float*)d_in[12];
    const float* b1 = (const float*)d_in[13];
    const float* mg = (const float*)d_in[14];
    const float* mb = (const float*)d_in[15];
    const float* W2 = (const float*)d_in[16];
    const float* b2 = (const float*)d_in[17];
    float* out = (float*)d_out;
    const int* srcp = eidx;
    const int* dstp = eidx + EE;

    float *h_, *hn_, *tmp_, *mid_, *vn_, *vnsum_, *inv_, *w1c_, *w2c_;
    cudaGetSymbolAddress((void**)&h_, g_h);
    cudaGetSymbolAddress((void**)&hn_, g_hn);
    cudaGetSymbolAddress((void**)&tmp_, g_tmp);
    cudaGetSymbolAddress((void**)&mid_, g_mid);
    cudaGetSymbolAddress((void**)&vn_, g_vn);
    cudaGetSymbolAddress((void**)&vnsum_, g_vnsum);
    cudaGetSymbolAddress((void**)&inv_, g_inv);
    cudaGetSymbolAddress((void**)&w1c_, g_w1c);
    cudaGetSymbolAddress((void**)&w2c_, g_w2c);

    const int NB_SCAN = (NN + 1023) / 1024;
    const int NW = 3 * HH * HB2;
    const int SMEM1 = 2 * 64 * 20 * 4 + 2 * 16 * 520 * 4;  // 76800 bytes

    cudaFuncSetAttribute(gemm1_ln, cudaFuncAttributeMaxDynamicSharedMemorySize, SMEM1);

    // ---- setup ----
    zero_setup<<<(NN + 255) / 256, 256>>>();
    count_deg<<<(EE + 255) / 256, 256>>>(dstp);
    count_batch<<<(NN + 255) / 256, 256>>>(batch);
    scan_block<<<NB_SCAN, 1024>>>();
    scan_sums<<<1, 128>>>(NB_SCAN);
    add_offs<<<(NN + 255) / 256, 256>>>();
    csr_fill<<<(EE + 255) / 256, 256>>>(dstp);
    calc_inv<<<(BBATCH + 255) / 256, 256>>>();
    vn_init<<<(BBATCH * HH + 255) / 256, 256>>>(vn_, vn_emb);
    cvt_w<<<(NW + 255) / 256, 256>>>(W1, w1c_, NW);
    cvt_w<<<(NW + 255) / 256, 256>>>(W2, w2c_, NW);
    node_enc<<<NN, 256>>>(x, node_W, node_b, h_);

    // ---- layers 1..3 ----
    for (int l = 1; l < LLAYERS; l++) {
        if (l == 1)
            ln_relu<HH, false><<<NN / 8, 256>>>(h_, hn_, ln_g + l * HH, ln_b + l * HH);
        else
            vn_ln_relu<<<NN / 8, 256>>>(h_, hn_, vn_, batch, ln_g + l * HH, ln_b + l * HH);
        aggregate<<<NN / 8, 256>>>(hn_, srcp, eattr, edge_W, edge_b, tt + (l - 1), tmp_);
        gemm1_ln<<<(NN + 63) / 64, 256, SMEM1>>>(
            tmp_, w1c_ + (size_t)(l - 1) * HH * HB2, b1 + (l - 1) * HB2,
            mg + (l - 1) * HB2, mb + (l - 1) * HB2, mid_, NN);
        dim3 g2(HH / 128, (NN + 127) / 128);
        gemm_tf32_pipe<<<g2, 128>>>(mid_, w2c_ + (size_t)(l - 1) * HB2 * HH,
                                    b2 + (l - 1) * HH, h_, NN, HB2, HH, 1);
        zero_f<<<(BBATCH * HH + 255) / 256, 256>>>(vnsum_, BBATCH * HH);
        pool_sum<<<(NN + 511) / 512, 256>>>(h_, batch, vnsum_);
        vn_update<<<(BBATCH * HH + 255) / 256, 256>>>(vn_, vnsum_, inv_);
    }

    // ---- final ----
    vn_ln_relu<<<NN / 8, 256>>>(h_, hn_, vn_, batch, ln_g, ln_b);
    zero_f<<<(BBATCH * HH + 255) / 256, 256>>>(out, BBATCH * HH);
    pool_sum<<<(NN + 511) / 512, 256>>>(hn_, batch, out);
    scale_out<<<(BBATCH * HH + 255) / 256, 256>>>(out, inv_);
}